// round 14
// baseline (speedup 1.0000x reference)
#include <cuda_runtime.h>
#include <cuda_bf16.h>
#include <mma.h>
#include <math.h>
#include <stdint.h>

using namespace nvcuda;

#define FULLMASK 0xffffffffu

// ---------------- problem constants ----------------
constexpr int Bb = 2, Ss = 2048, Dd = 2048;
constexpr int Zz = 512, HDim = 4096, Hh = 8, EN = 8;
constexpr int ZH = 64, VH = 512;
constexpr int Gg = 32, DG = 64;
constexpr int BHh = Bb * Hh;
constexpr float EPSC = 1e-5f;
constexpr int NC = 16, CLk = Ss / NC;   // cema chunks
constexpr int NZR = Zz + HDim;          // fused z|r output width = 4608

// ---------------- scratch ----------------
__device__ float g_cema[Bb * Ss * Dd];
__device__ float g_r   [Bb * Ss * HDim];
__device__ float g_scores[(size_t)BHh * Ss * Ss];
__device__ float g_p1[Bb * Gg * Ss];
__device__ float g_p2[Bb * Gg * Ss];
__device__ float g_c1[Bb * Gg * Ss];
__device__ float g_c2[Bb * Gg * Ss];
__device__ float g_coef[6][Dd * EN];
// cema chunk states
__device__ float g_sr[Bb][NC][EN][Dd], g_si[Bb][NC][EN][Dd];
__device__ float g_er[Bb][NC][EN][Dd], g_ei[Bb][NC][EN][Dd];

// bf16 hi/lo operands
__device__ __nv_bfloat16 g_tsnh[Bb * Ss * Dd],  g_tsnl[Bb * Ss * Dd];
__device__ __nv_bfloat16 g_mxh [Bb * Ss * Dd],  g_mxl [Bb * Ss * Dd];
__device__ __nv_bfloat16 g_vh  [Bb * Ss * HDim], g_vl [Bb * Ss * HDim];
__device__ __nv_bfloat16 g_ath [Bb * Ss * HDim], g_atl[Bb * Ss * HDim];
__device__ __nv_bfloat16 g_ph[(size_t)BHh * Ss * Ss], g_pl[(size_t)BHh * Ss * Ss];
__device__ __nv_bfloat16 g_qh [BHh * Ss * ZH],  g_ql [BHh * Ss * ZH];
__device__ __nv_bfloat16 g_kth[BHh * ZH * Ss],  g_ktl[BHh * ZH * Ss];
// weight splits (wz and wr fused column-wise into wzr[K, 4608])
__device__ __nv_bfloat16 g_wzrh[Dd * NZR],  g_wzrl[Dd * NZR];
__device__ __nv_bfloat16 g_wvh [Dd * HDim], g_wvl [Dd * HDim];
__device__ __nv_bfloat16 g_wh1h[Dd * Dd],   g_wh1l[Dd * Dd];
__device__ __nv_bfloat16 g_wh2h[HDim * Dd], g_wh2l[HDim * Dd];

// ---------------- helpers ----------------
__device__ __forceinline__ float sigmoidf_(float x) { return 1.f / (1.f + __expf(-x)); }

__device__ __forceinline__ void bsplit(float v, __nv_bfloat16& h, __nv_bfloat16& l) {
    h = __float2bfloat16(v);
    l = __float2bfloat16(v - __bfloat162float(h));
}

__device__ __forceinline__ uint32_t smem_u32(const void* p) {
    uint32_t a;
    asm("{ .reg .u64 t; cvta.to.shared.u64 t, %1; cvt.u32.u64 %0, t; }" : "=r"(a) : "l"(p));
    return a;
}

#define CP16(dst, src) \
    asm volatile("cp.async.cg.shared.global [%0], [%1], 16;" :: "r"(dst), "l"(src))
#define CP_COMMIT() asm volatile("cp.async.commit_group;" ::: "memory")
#define CP_WAIT0()  asm volatile("cp.async.wait_group 0;" ::: "memory")

// ---------------- batched split kernel w/ strided destinations ----------------
struct SplitArgs {
    const float* src[5];
    __nv_bfloat16 *h[5], *l[5];
    int cum[6];
    int srcW4[5];
    int dstStride4[5];
    int dstOff4[5];
};

__global__ void splitk_all(SplitArgs sa) {
    int i = blockIdx.x * blockDim.x + threadIdx.x;
    if (i >= sa.cum[5]) return;
    int s = 0;
    while (i >= sa.cum[s + 1]) s++;
    int j = i - sa.cum[s];
    int srow = j / sa.srcW4[s];
    int scol = j - srow * sa.srcW4[s];
    size_t dj = (size_t)srow * sa.dstStride4[s] + sa.dstOff4[s] + scol;
    float4 v = *(const float4*)(sa.src[s] + (size_t)j * 4);
    __nv_bfloat16 h0, l0, h1, l1, h2, l2, h3, l3;
    bsplit(v.x, h0, l0); bsplit(v.y, h1, l1);
    bsplit(v.z, h2, l2); bsplit(v.w, h3, l3);
    __nv_bfloat162* hp = (__nv_bfloat162*)(sa.h[s] + dj * 4);
    __nv_bfloat162* lp = (__nv_bfloat162*)(sa.l[s] + dj * 4);
    hp[0] = __nv_bfloat162{h0, h1}; hp[1] = __nv_bfloat162{h2, h3};
    lp[0] = __nv_bfloat162{l0, l1}; lp[1] = __nv_bfloat162{l2, l3};
}

// ==================================================================
// hgemm: bf16 hi/lo 3-product GEMM, 2-stage cp.async double buffer
// 128x128x32 CTA tile, 128 threads, 4 warps (2x2), warp tile 64x64
// ==================================================================
constexpr int ALD = 40;
constexpr int BLD = 136;
constexpr int CLD = 132;
constexpr int ST_AH = 0;
constexpr int ST_AL = ST_AH + 128 * ALD * 2;
constexpr int ST_BH = ST_AL + 128 * ALD * 2;
constexpr int ST_BL = ST_BH + 32 * BLD * 2;
constexpr int ST_SZ = ST_BL + 32 * BLD * 2;        // 37888
constexpr int HG_SMEM = (2 * ST_SZ > 128 * CLD * 4) ? 2 * ST_SZ : 128 * CLD * 4; // 75776

struct HgArgs {
    const __nv_bfloat16 *Ah, *Al, *Bh, *Bl;
    const __nv_bfloat16 *A2h, *A2l, *B2h, *B2l;
    const float *bias, *resid, *bias2;
    const float *freqs, *agam, *abeta;
    float *C, *C2;
    __nv_bfloat16 *Ch, *Cl;
    int M, N, K, K1, lda1, lda2, ldb;
};

template <bool FUSE>
__device__ __forceinline__ void hg_load_stage(uint32_t sb, const HgArgs& a,
                                              int m0, int n0, int k0, int tid) {
    const __nv_bfloat16 *Ah, *Al, *Bh, *Bl;
    int lda, kr;
    if (FUSE && k0 >= a.K1) {
        Ah = a.A2h; Al = a.A2l; Bh = a.B2h; Bl = a.B2l;
        lda = a.lda2; kr = k0 - a.K1;
    } else {
        Ah = a.Ah; Al = a.Al; Bh = a.Bh; Bl = a.Bl;
        lda = a.lda1; kr = k0;
    }
    #pragma unroll
    for (int i = 0; i < 4; i++) {
        int chunk = i * 128 + tid;
        int row = chunk >> 2, c = (chunk & 3) * 8;
        size_t go = (size_t)(m0 + row) * lda + kr + c;
        uint32_t so = sb + (uint32_t)((row * ALD + c) * 2);
        CP16(so + ST_AH, Ah + go);
        CP16(so + ST_AL, Al + go);
    }
    #pragma unroll
    for (int i = 0; i < 4; i++) {
        int chunk = i * 128 + tid;
        int row = chunk >> 4, c = (chunk & 15) * 8;
        size_t go = (size_t)(kr + row) * a.ldb + n0 + c;
        uint32_t so = sb + (uint32_t)((row * BLD + c) * 2);
        CP16(so + ST_BH, Bh + go);
        CP16(so + ST_BL, Bl + go);
    }
}

__device__ __forceinline__ void hg_mma64(char* st, int wm, int wn,
    wmma::fragment<wmma::accumulator, 16, 16, 16, float> (&acc)[4][4]) {
    __nv_bfloat16* Ah = (__nv_bfloat16*)(st + ST_AH);
    __nv_bfloat16* Al = (__nv_bfloat16*)(st + ST_AL);
    __nv_bfloat16* Bh = (__nv_bfloat16*)(st + ST_BH);
    __nv_bfloat16* Bl = (__nv_bfloat16*)(st + ST_BL);
    #pragma unroll
    for (int kk = 0; kk < 2; kk++) {
        wmma::fragment<wmma::matrix_a, 16, 16, 16, __nv_bfloat16, wmma::row_major> fah[4], fal[4];
        #pragma unroll
        for (int r = 0; r < 4; r++) {
            wmma::load_matrix_sync(fah[r], Ah + (wm + r * 16) * ALD + kk * 16, ALD);
            wmma::load_matrix_sync(fal[r], Al + (wm + r * 16) * ALD + kk * 16, ALD);
        }
        #pragma unroll
        for (int c = 0; c < 4; c++) {
            wmma::fragment<wmma::matrix_b, 16, 16, 16, __nv_bfloat16, wmma::row_major> fbh, fbl;
            wmma::load_matrix_sync(fbh, Bh + (kk * 16) * BLD + wn + c * 16, BLD);
            wmma::load_matrix_sync(fbl, Bl + (kk * 16) * BLD + wn + c * 16, BLD);
            #pragma unroll
            for (int r = 0; r < 4; r++) {
                wmma::mma_sync(acc[r][c], fah[r], fbh, acc[r][c]);
                wmma::mma_sync(acc[r][c], fah[r], fbl, acc[r][c]);
                wmma::mma_sync(acc[r][c], fal[r], fbh, acc[r][c]);
            }
        }
    }
}

template <bool SILU, bool RESID, bool BIAS, bool OUTHL, bool FUSE, bool ZR>
__global__ void __launch_bounds__(128) hgemm(HgArgs a) {
    extern __shared__ char sm[];
    const uint32_t sb0 = smem_u32(sm);
    float* Ct = (float*)sm;
    const int tid = threadIdx.x;
    const int wid = tid >> 5;
    const int m0 = blockIdx.y * 128;
    const int n0 = blockIdx.x * 128;
    const int wm = (wid & 1) * 64;
    const int wn = (wid >> 1) * 64;

    wmma::fragment<wmma::accumulator, 16, 16, 16, float> acc[4][4];
    #pragma unroll
    for (int r = 0; r < 4; r++)
        #pragma unroll
        for (int c = 0; c < 4; c++) wmma::fill_fragment(acc[r][c], 0.f);

    const int nk = a.K / 32;
    hg_load_stage<FUSE>(sb0, a, m0, n0, 0, tid);
    CP_COMMIT();

    for (int it = 0; it < nk; it++) {
        CP_WAIT0();
        __syncthreads();
        if (it + 1 < nk) {
            hg_load_stage<FUSE>(sb0 + ((it + 1) & 1) * ST_SZ, a, m0, n0, (it + 1) * 32, tid);
            CP_COMMIT();
        }
        hg_mma64(sm + (it & 1) * ST_SZ, wm, wn, acc);
    }
    __syncthreads();

    #pragma unroll
    for (int r = 0; r < 4; r++)
        #pragma unroll
        for (int c = 0; c < 4; c++)
            wmma::store_matrix_sync(Ct + (wm + r * 16) * CLD + wn + c * 16,
                                    acc[r][c], CLD, wmma::mem_row_major);
    __syncthreads();

    #pragma unroll
    for (int i = 0; i < 32; i++) {
        int flat = i * 128 + tid;
        int row = flat >> 5, col4 = (flat & 31) * 4;
        if (ZR) {
            int n = n0 + col4;
            int grow = m0 + row;
            int b = grow / Ss, s = grow - b * Ss;
            if (n < Zz) {
                // fused head-RMS + gamma/beta + rotary -> q/k bf16 hi/lo
                float z0 = Ct[row * CLD + col4 + 0] + a.bias[n + 0];
                float z1 = Ct[row * CLD + col4 + 1] + a.bias[n + 1];
                float z2 = Ct[row * CLD + col4 + 2] + a.bias[n + 2];
                float z3 = Ct[row * CLD + col4 + 3] + a.bias[n + 3];
                float ssq = z0 * z0 + z1 * z1 + z2 * z2 + z3 * z3;
                // reduce over the 16 lanes covering this row's 64-wide head
                #pragma unroll
                for (int o = 1; o < 16; o <<= 1)
                    ssq += __shfl_xor_sync(FULLMASK, ssq, o);
                float inv = rsqrtf(ssq / (float)ZH + EPSC);
                z0 *= inv; z1 *= inv; z2 *= inv; z3 *= inv;
                const float c0 = 0.125f;  // 1/sqrt(ZH)
                float q0 = z0 * ((a.agam[n + 0] + 1.f) * c0) + a.abeta[n + 0];
                float q1 = z1 * ((a.agam[n + 1] + 1.f) * c0) + a.abeta[n + 1];
                float q2 = z2 * ((a.agam[n + 2] + 1.f) * c0) + a.abeta[n + 2];
                float q3 = z3 * ((a.agam[n + 3] + 1.f) * c0) + a.abeta[n + 3];
                float k0 = z0 * ((a.agam[Zz + n + 0] + 1.f) * c0) + a.abeta[Zz + n + 0];
                float k1 = z1 * ((a.agam[Zz + n + 1] + 1.f) * c0) + a.abeta[Zz + n + 1];
                float k2 = z2 * ((a.agam[Zz + n + 2] + 1.f) * c0) + a.abeta[Zz + n + 2];
                float k3 = z3 * ((a.agam[Zz + n + 3] + 1.f) * c0) + a.abeta[Zz + n + 3];
                int h = n >> 6, hcol = n & 63;
                int p0 = hcol >> 1;           // first rotary pair index (0..31)
                float cv0 = a.freqs[(s * 32 + p0) * 2 + 0];
                float sv0 = a.freqs[(s * 32 + p0) * 2 + 1];
                float cv1 = a.freqs[(s * 32 + p0 + 1) * 2 + 0];
                float sv1 = a.freqs[(s * 32 + p0 + 1) * 2 + 1];
                float qa = q0 * cv0 - q1 * sv0, qb = q0 * sv0 + q1 * cv0;
                float qc = q2 * cv1 - q3 * sv1, qd = q2 * sv1 + q3 * cv1;
                float ka = k0 * cv0 - k1 * sv0, kb = k0 * sv0 + k1 * cv0;
                float kc = k2 * cv1 - k3 * sv1, kd = k2 * sv1 + k3 * cv1;

                size_t qbase = ((size_t)(b * Hh + h) * Ss + s) * ZH + hcol;
                __nv_bfloat16 hh0, ll0, hh1, ll1, hh2, ll2, hh3, ll3;
                bsplit(qa, hh0, ll0); bsplit(qb, hh1, ll1);
                bsplit(qc, hh2, ll2); bsplit(qd, hh3, ll3);
                __nv_bfloat162* qhp = (__nv_bfloat162*)(g_qh + qbase);
                __nv_bfloat162* qlp = (__nv_bfloat162*)(g_ql + qbase);
                qhp[0] = __nv_bfloat162{hh0, hh1}; qhp[1] = __nv_bfloat162{hh2, hh3};
                qlp[0] = __nv_bfloat162{ll0, ll1}; qlp[1] = __nv_bfloat162{ll2, ll3};

                size_t kbase = ((size_t)(b * Hh + h) * ZH + hcol) * Ss + s;
                bsplit(ka, hh0, ll0); bsplit(kb, hh1, ll1);
                bsplit(kc, hh2, ll2); bsplit(kd, hh3, ll3);
                g_kth[kbase + 0 * Ss] = hh0; g_ktl[kbase + 0 * Ss] = ll0;
                g_kth[kbase + 1 * Ss] = hh1; g_ktl[kbase + 1 * Ss] = ll1;
                g_kth[kbase + 2 * Ss] = hh2; g_ktl[kbase + 2 * Ss] = ll2;
                g_kth[kbase + 3 * Ss] = hh3; g_ktl[kbase + 3 * Ss] = ll3;
            } else {
                int nr = n - Zz;
                float v[4];
                #pragma unroll
                for (int e = 0; e < 4; e++) {
                    float cv = Ct[row * CLD + col4 + e] + a.bias2[nr + e];
                    v[e] = cv * sigmoidf_(cv);
                }
                float4 o; o.x = v[0]; o.y = v[1]; o.z = v[2]; o.w = v[3];
                *(float4*)(a.C2 + (size_t)grow * HDim + nr) = o;
            }
        } else {
            size_t goff = (size_t)(m0 + row) * a.N + n0 + col4;
            float v[4];
            #pragma unroll
            for (int e = 0; e < 4; e++) {
                float cv = Ct[row * CLD + col4 + e];
                if (BIAS)  cv += a.bias[n0 + col4 + e];
                if (RESID) cv += a.resid[goff + e];
                if (SILU)  cv = cv * sigmoidf_(cv);
                v[e] = cv;
            }
            if (OUTHL) {
                __nv_bfloat16 h0, l0, h1, l1, h2, l2, h3, l3;
                bsplit(v[0], h0, l0); bsplit(v[1], h1, l1);
                bsplit(v[2], h2, l2); bsplit(v[3], h3, l3);
                __nv_bfloat162* hp = (__nv_bfloat162*)(a.Ch + goff);
                __nv_bfloat162* lp = (__nv_bfloat162*)(a.Cl + goff);
                hp[0] = __nv_bfloat162{h0, h1}; hp[1] = __nv_bfloat162{h2, h3};
                lp[0] = __nv_bfloat162{l0, l1}; lp[1] = __nv_bfloat162{l2, l3};
            } else {
                float4 o; o.x = v[0]; o.y = v[1]; o.z = v[2]; o.w = v[3];
                *(float4*)(a.C + goff) = o;
            }
        }
    }
}

// ==================================================================
// pv_hgemm: attn = (P @ V) * r -> bf16 hi/lo, 128 threads, 64x64 warp tile
// ==================================================================
__global__ void __launch_bounds__(128) pv_hgemm(const float* __restrict__ rgate) {
    extern __shared__ char sm[];
    const uint32_t sb0 = smem_u32(sm);
    float* Ct = (float*)sm;
    const int tid = threadIdx.x;
    const int wid = tid >> 5;
    const int nt = blockIdx.x;
    const int qt = (int)gridDim.y - 1 - (int)blockIdx.y;  // heavy tiles first
    const int bh = blockIdx.z;
    const int b = bh >> 3, h = bh & 7;
    const int wm = (wid & 1) * 64;
    const int wn = (wid >> 1) * 64;

    HgArgs a;
    a.Ah = g_ph + (size_t)bh * Ss * Ss + (size_t)(qt * 128) * Ss;
    a.Al = g_pl + (size_t)bh * Ss * Ss + (size_t)(qt * 128) * Ss;
    a.Bh = g_vh + (size_t)b * Ss * HDim + h * VH + nt * 128;
    a.Bl = g_vl + (size_t)b * Ss * HDim + h * VH + nt * 128;
    a.lda1 = Ss; a.ldb = HDim; a.K1 = 1 << 30;

    wmma::fragment<wmma::accumulator, 16, 16, 16, float> acc[4][4];
    #pragma unroll
    for (int r = 0; r < 4; r++)
        #pragma unroll
        for (int c = 0; c < 4; c++) wmma::fill_fragment(acc[r][c], 0.f);

    const int nk = (qt + 1) * 4;
    hg_load_stage<false>(sb0, a, 0, 0, 0, tid);
    CP_COMMIT();

    for (int it = 0; it < nk; it++) {
        CP_WAIT0();
        __syncthreads();
        if (it + 1 < nk) {
            hg_load_stage<false>(sb0 + ((it + 1) & 1) * ST_SZ, a, 0, 0, (it + 1) * 32, tid);
            CP_COMMIT();
        }
        hg_mma64(sm + (it & 1) * ST_SZ, wm, wn, acc);
    }
    __syncthreads();

    #pragma unroll
    for (int r = 0; r < 4; r++)
        #pragma unroll
        for (int c = 0; c < 4; c++)
            wmma::store_matrix_sync(Ct + (wm + r * 16) * CLD + wn + c * 16,
                                    acc[r][c], CLD, wmma::mem_row_major);
    __syncthreads();

    #pragma unroll
    for (int i = 0; i < 32; i++) {
        int flat = i * 128 + tid;
        int row = flat >> 5, col4 = (flat & 31) * 4;
        int q = qt * 128 + row;
        size_t goff = ((size_t)b * Ss + q) * HDim + h * VH + nt * 128 + col4;
        float4 rg = *(const float4*)(rgate + goff);
        float v0 = Ct[row * CLD + col4 + 0] * rg.x;
        float v1 = Ct[row * CLD + col4 + 1] * rg.y;
        float v2 = Ct[row * CLD + col4 + 2] * rg.z;
        float v3 = Ct[row * CLD + col4 + 3] * rg.w;
        __nv_bfloat16 h0, l0, h1, l1, h2, l2, h3, l3;
        bsplit(v0, h0, l0); bsplit(v1, h1, l1);
        bsplit(v2, h2, l2); bsplit(v3, h3, l3);
        __nv_bfloat162* hp = (__nv_bfloat162*)(g_ath + goff);
        __nv_bfloat162* lp = (__nv_bfloat162*)(g_atl + goff);
        hp[0] = __nv_bfloat162{h0, h1}; hp[1] = __nv_bfloat162{h2, h3};
        lp[0] = __nv_bfloat162{l0, l1}; lp[1] = __nv_bfloat162{l2, l3};
    }
}

// ==================================================================
// Attention scores via WMMA: triangular CTA grid (no empty CTAs),
// 128 threads, 4 warps (2x2), warp tile 64x64 (ratio 3)
// ==================================================================
constexpr int SC_QLD = 72;
constexpr int SC_KLD = 136;
constexpr int SC_QH = 0;
constexpr int SC_QL = SC_QH + 128 * SC_QLD * 2;
constexpr int SC_KH = SC_QL + 128 * SC_QLD * 2;
constexpr int SC_KL = SC_KH + 64 * SC_KLD * 2;
constexpr int SC_SMEM = SC_KL + 64 * SC_KLD * 2;
constexpr int SC_NT = Ss / 128;
constexpr int SC_TRI = SC_NT * (SC_NT + 1) / 2;

__global__ void __launch_bounds__(128) attn_scores_mma() {
    int t = blockIdx.x;
    int qt = (int)((sqrtf(8.f * (float)t + 1.f) - 1.f) * 0.5f);
    while ((qt + 1) * (qt + 2) / 2 <= t) qt++;
    while (qt * (qt + 1) / 2 > t) qt--;
    int kt = t - qt * (qt + 1) / 2;
    int bh = blockIdx.z;

    extern __shared__ char sm[];
    __nv_bfloat16* Qh = (__nv_bfloat16*)(sm + SC_QH);
    __nv_bfloat16* Ql = (__nv_bfloat16*)(sm + SC_QL);
    __nv_bfloat16* Kh = (__nv_bfloat16*)(sm + SC_KH);
    __nv_bfloat16* Kl = (__nv_bfloat16*)(sm + SC_KL);
    const int tid = threadIdx.x;
    const int wid = tid >> 5;
    const int wm = (wid & 1) * 64;
    const int wn = (wid >> 1) * 64;

    const __nv_bfloat16* qsrc_h = g_qh + ((size_t)bh * Ss + qt * 128) * ZH;
    const __nv_bfloat16* qsrc_l = g_ql + ((size_t)bh * Ss + qt * 128) * ZH;
    const __nv_bfloat16* ksrc_h = g_kth + (size_t)bh * ZH * Ss + kt * 128;
    const __nv_bfloat16* ksrc_l = g_ktl + (size_t)bh * ZH * Ss + kt * 128;

    #pragma unroll
    for (int i = 0; i < 8; i++) {
        int flat = i * 128 + tid;
        int row = flat >> 3, c8 = (flat & 7) * 8;
        *(uint4*)(Qh + row * SC_QLD + c8) = *(const uint4*)(qsrc_h + row * ZH + c8);
        *(uint4*)(Ql + row * SC_QLD + c8) = *(const uint4*)(qsrc_l + row * ZH + c8);
    }
    #pragma unroll
    for (int i = 0; i < 8; i++) {
        int flat = i * 128 + tid;
        int row = flat >> 4, c8 = (flat & 15) * 8;
        *(uint4*)(Kh + row * SC_KLD + c8) = *(const uint4*)(ksrc_h + (size_t)row * Ss + c8);
        *(uint4*)(Kl + row * SC_KLD + c8) = *(const uint4*)(ksrc_l + (size_t)row * Ss + c8);
    }
    __syncthreads();

    wmma::fragment<wmma::accumulator, 16, 16, 16, float> acc[4][4];
    #pragma unroll
    for (int r = 0; r < 4; r++)
        #pragma unroll
        for (int c = 0; c < 4; c++) wmma::fill_fragment(acc[r][c], 0.f);

    #pragma unroll
    for (int kk = 0; kk < 4; kk++) {
        wmma::fragment<wmma::matrix_a, 16, 16, 16, __nv_bfloat16, wmma::row_major> fah[4], fal[4];
        #pragma unroll
        for (int r = 0; r < 4; r++) {
            wmma::load_matrix_sync(fah[r], Qh + (wm + r * 16) * SC_QLD + kk * 16, SC_QLD);
            wmma::load_matrix_sync(fal[r], Ql + (wm + r * 16) * SC_QLD + kk * 16, SC_QLD);
        }
        #pragma unroll
        for (int c = 0; c < 4; c++) {
            wmma::fragment<wmma::matrix_b, 16, 16, 16, __nv_bfloat16, wmma::row_major> fbh, fbl;
            wmma::load_matrix_sync(fbh, Kh + (kk * 16) * SC_KLD + wn + c * 16, SC_KLD);
            wmma::load_matrix_sync(fbl, Kl + (kk * 16) * SC_KLD + wn + c * 16, SC_KLD);
            #pragma unroll
            for (int r = 0; r < 4; r++) {
                wmma::mma_sync(acc[r][c], fah[r], fbh, acc[r][c]);
                wmma::mma_sync(acc[r][c], fah[r], fbl, acc[r][c]);
                wmma::mma_sync(acc[r][c], fal[r], fbh, acc[r][c]);
            }
        }
    }

    #pragma unroll
    for (int r = 0; r < 4; r++)
        #pragma unroll
        for (int c = 0; c < 4; c++)
            wmma::store_matrix_sync(
                g_scores + ((size_t)bh * Ss + qt * 128 + wm + r * 16) * Ss + kt * 128 + wn + c * 16,
                acc[r][c], Ss, wmma::mem_row_major);
}

// ==================================================================
// Timestep norm
// ==================================================================
__global__ void tsn_partial(const float* __restrict__ x) {
    int warp = (blockIdx.x * blockDim.x + threadIdx.x) >> 5;
    int lane = threadIdx.x & 31;
    if (warp >= Bb * Ss * Gg) return;
    int g = warp % Gg;
    int s = (warp / Gg) % Ss;
    int b = warp / (Gg * Ss);
    const float* p = x + ((size_t)(b * Ss + s)) * Dd + g * DG;
    float v0 = p[lane], v1 = p[lane + 32];
    float s1 = v0 + v1;
    float s2 = v0 * v0 + v1 * v1;
    #pragma unroll
    for (int o = 16; o; o >>= 1) {
        s1 += __shfl_down_sync(FULLMASK, s1, o);
        s2 += __shfl_down_sync(FULLMASK, s2, o);
    }
    if (lane == 0) {
        int idx = (b * Gg + g) * Ss + s;
        g_p1[idx] = s1;
        g_p2[idx] = s2;
    }
}

__global__ void tsn_scan() {
    int bg = blockIdx.x;
    int t  = threadIdx.x;
    const float* r1 = g_p1 + bg * Ss;
    const float* r2 = g_p2 + bg * Ss;
    float v1[8], v2[8];
    float a1 = 0.f, a2 = 0.f;
    #pragma unroll
    for (int i = 0; i < 8; i++) {
        a1 += r1[t * 8 + i]; v1[i] = a1;
        a2 += r2[t * 8 + i]; v2[i] = a2;
    }
    __shared__ float sh1[256], sh2[256];
    sh1[t] = a1; sh2[t] = a2;
    __syncthreads();
    for (int off = 1; off < 256; off <<= 1) {
        float b1 = 0.f, b2 = 0.f;
        if (t >= off) { b1 = sh1[t - off]; b2 = sh2[t - off]; }
        __syncthreads();
        sh1[t] += b1; sh2[t] += b2;
        __syncthreads();
    }
    float o1 = t ? sh1[t - 1] : 0.f;
    float o2 = t ? sh2[t - 1] : 0.f;
    float* w1 = g_c1 + bg * Ss;
    float* w2 = g_c2 + bg * Ss;
    #pragma unroll
    for (int i = 0; i < 8; i++) {
        w1[t * 8 + i] = v1[i] + o1;
        w2[t * 8 + i] = v2[i] + o2;
    }
}

__global__ void tsn_norm(const float* __restrict__ x, const float* __restrict__ w,
                         const float* __restrict__ bias) {
    int i4 = blockIdx.x * blockDim.x + threadIdx.x;
    if (i4 >= Bb * Ss * Dd / 4) return;
    int d4 = i4 % (Dd / 4);
    int s  = (i4 / (Dd / 4)) % Ss;
    int b  = i4 / (Dd / 4 * Ss);
    int d  = d4 * 4;
    int g  = d / DG;
    int ci = (b * Gg + g) * Ss + s;
    float cnt  = (float)(s + 1) * (float)DG;
    float mean = g_c1[ci] / cnt;
    float var  = g_c2[ci] / cnt - mean * mean;
    float inv  = rsqrtf(var + EPSC);
    float4 xv = *(const float4*)(x + (size_t)i4 * 4);
    float4 wv = *(const float4*)(w + d);
    float4 bv = *(const float4*)(bias + d);
    float4 o;
    o.x = (xv.x - mean) * inv * wv.x + bv.x;
    o.y = (xv.y - mean) * inv * wv.y + bv.y;
    o.z = (xv.z - mean) * inv * wv.z + bv.z;
    o.w = (xv.w - mean) * inv * wv.w + bv.w;
    __nv_bfloat16 h0, l0, h1, l1, h2, l2, h3, l3;
    bsplit(o.x, h0, l0); bsplit(o.y, h1, l1);
    bsplit(o.z, h2, l2); bsplit(o.w, h3, l3);
    __nv_bfloat162* hp = (__nv_bfloat162*)(g_tsnh + (size_t)i4 * 4);
    __nv_bfloat162* lp = (__nv_bfloat162*)(g_tsnl + (size_t)i4 * 4);
    hp[0] = __nv_bfloat162{h0, h1}; hp[1] = __nv_bfloat162{h2, h3};
    lp[0] = __nv_bfloat162{l0, l1}; lp[1] = __nv_bfloat162{l2, l3};
}

// ==================================================================
// CEMA (chunked scan, reads tsn from bf16 hi/lo)
// ==================================================================
__device__ __forceinline__ float tsn_at(size_t idx) {
    return __bfloat162float(g_tsnh[idx]) + __bfloat162float(g_tsnl[idx]);
}

__global__ void cema_coef(const float* __restrict__ alpha, const float* __restrict__ delta,
                          const float* __restrict__ theta, const float* __restrict__ gamma) {
    int i = blockIdx.x * blockDim.x + threadIdx.x;
    if (i >= Dd * EN) return;
    int d = i / EN, n = i % EN;
    float p  = 1.f / (1.f + expf(-alpha[i]));
    float qm = 1.f - p * (1.f / (1.f + expf(-delta[i])));
    float th = 1.f / (1.f + expf(-theta[d]));
    float ph = th * (2.f * 3.14159265358979323846f * (float)(n + 1) / (float)EN);
    float c = cosf(ph), s = sinf(ph);
    g_coef[0][i] = qm * c;
    g_coef[1][i] = qm * s;
    g_coef[2][i] = p * c;
    g_coef[3][i] = p * s;
    g_coef[4][i] = gamma[i * 2 + 0];
    g_coef[5][i] = gamma[i * 2 + 1];
}

__global__ void cema_local() {
    int gt = blockIdx.x * blockDim.x + threadIdx.x;
    if (gt >= Bb * NC * Dd) return;
    int d = gt % Dd;
    int c = (gt / Dd) % NC;
    int b = gt / (Dd * NC);
    float qr[8], qi[8], ur[8], ui[8], hr[8], hi[8];
    #pragma unroll
    for (int n = 0; n < EN; n++) {
        int ci = d * EN + n;
        qr[n] = g_coef[0][ci]; qi[n] = g_coef[1][ci];
        ur[n] = g_coef[2][ci]; ui[n] = g_coef[3][ci];
        hr[n] = 0.f; hi[n] = 0.f;
    }
    size_t base = ((size_t)b * Ss + c * CLk) * Dd + d;
    float xv = tsn_at(base);
    for (int t = 0; t < CLk; t++) {
        float xnext = (t + 1 < CLk) ? tsn_at(base + (size_t)(t + 1) * Dd) : 0.f;
        #pragma unroll
        for (int n = 0; n < EN; n++) {
            float nhr = fmaf(qr[n], hr[n], fmaf(-qi[n], hi[n], ur[n] * xv));
            float nhi = fmaf(qi[n], hr[n], fmaf(qr[n], hi[n], ui[n] * xv));
            hr[n] = nhr; hi[n] = nhi;
        }
        xv = xnext;
    }
    #pragma unroll
    for (int n = 0; n < EN; n++) {
        g_sr[b][c][n][d] = hr[n];
        g_si[b][c][n][d] = hi[n];
    }
}

__global__ void cema_prop() {
    int gt = blockIdx.x * blockDim.x + threadIdx.x;
    if (gt >= Bb * Dd) return;
    int d = gt % Dd, b = gt / Dd;
    #pragma unroll
    for (int n = 0; n < EN; n++) {
        int ci = d * EN + n;
        float pr = g_coef[0][ci], pi = g_coef[1][ci];
        #pragma unroll
        for (int s = 0; s < 7; s++) {
            float nr = pr * pr - pi * pi;
            float ni = 2.f * pr * pi;
            pr = nr; pi = ni;
        }
        float er = 0.f, ei = 0.f;
        for (int c = 0; c < NC; c++) {
            g_er[b][c][n][d] = er;
            g_ei[b][c][n][d] = ei;
            float sr = g_sr[b][c][n][d], si = g_si[b][c][n][d];
            float nr = fmaf(pr, er, fmaf(-pi, ei, sr));
            float ni = fmaf(pi, er, fmaf(pr, ei, si));
            er = nr; ei = ni;
        }
    }
}

__global__ void cema_final(const float* __restrict__ omega) {
    int gt = blockIdx.x * blockDim.x + threadIdx.x;
    if (gt >= Bb * NC * Dd) return;
    int d = gt % Dd;
    int c = (gt / Dd) % NC;
    int b = gt / (Dd * NC);
    float qr[8], qi[8], ur[8], ui[8], gr[8], gi[8], hr[8], hi[8];
    #pragma unroll
    for (int n = 0; n < EN; n++) {
        int ci = d * EN + n;
        qr[n] = g_coef[0][ci]; qi[n] = g_coef[1][ci];
        ur[n] = g_coef[2][ci]; ui[n] = g_coef[3][ci];
        gr[n] = g_coef[4][ci]; gi[n] = g_coef[5][ci];
        hr[n] = g_er[b][c][n][d];
        hi[n] = g_ei[b][c][n][d];
    }
    float om = omega[d];
    size_t base = ((size_t)b * Ss + c * CLk) * Dd + d;
    float* op = g_cema + base;
    float xv = tsn_at(base);
    for (int t = 0; t < CLk; t++) {
        float xnext = (t + 1 < CLk) ? tsn_at(base + (size_t)(t + 1) * Dd) : 0.f;
        float y = 0.f;
        #pragma unroll
        for (int n = 0; n < EN; n++) {
            float nhr = fmaf(qr[n], hr[n], fmaf(-qi[n], hi[n], ur[n] * xv));
            float nhi = fmaf(qi[n], hr[n], fmaf(qr[n], hi[n], ui[n] * xv));
            hr[n] = nhr; hi[n] = nhi;
            y = fmaf(nhr, gr[n], fmaf(nhi, gi[n], y));
        }
        op[(size_t)t * Dd] = fmaf(xv, om, y);
        xv = xnext;
    }
}

// ==================================================================
// RMSNorm over D -> mx hi/lo
// ==================================================================
__global__ void rms_mx(const float* __restrict__ w) {
    int row = blockIdx.x;
    int t = threadIdx.x;
    const float* xr = g_cema + (size_t)row * Dd;
    float4 xv[2];
    float ss = 0.f;
    #pragma unroll
    for (int i = 0; i < 2; i++) {
        xv[i] = *(const float4*)(xr + (t + i * 256) * 4);
        ss += xv[i].x * xv[i].x + xv[i].y * xv[i].y + xv[i].z * xv[i].z + xv[i].w * xv[i].w;
    }
    __shared__ float sh[32];
    int lane = t & 31, wp = t >> 5;
    #pragma unroll
    for (int o = 16; o; o >>= 1) ss += __shfl_xor_sync(FULLMASK, ss, o);
    if (lane == 0) sh[wp] = ss;
    __syncthreads();
    if (wp == 0) {
        float v = (lane < 8) ? sh[lane] : 0.f;
        #pragma unroll
        for (int o = 16; o; o >>= 1) v += __shfl_xor_sync(FULLMASK, v, o);
        if (lane == 0) sh[0] = v;
    }
    __syncthreads();
    float inv = rsqrtf(sh[0] / (float)Dd + EPSC);
    #pragma unroll
    for (int i = 0; i < 2; i++) {
        int c = (t + i * 256) * 4;
        float4 wv = *(const float4*)(w + c);
        float o0 = xv[i].x * inv * wv.x;
        float o1 = xv[i].y * inv * wv.y;
        float o2 = xv[i].z * inv * wv.z;
        float o3 = xv[i].w * inv * wv.w;
        __nv_bfloat16 h0, l0, h1, l1, h2, l2, h3, l3;
        bsplit(o0, h0, l0); bsplit(o1, h1, l1);
        bsplit(o2, h2, l2); bsplit(o3, h3, l3);
        size_t off = (size_t)row * Dd + c;
        __nv_bfloat162* hp = (__nv_bfloat162*)(g_mxh + off);
        __nv_bfloat162* lp = (__nv_bfloat162*)(g_mxl + off);
        hp[0] = __nv_bfloat162{h0, h1}; hp[1] = __nv_bfloat162{h2, h3};
        lp[0] = __nv_bfloat162{l0, l1}; lp[1] = __nv_bfloat162{l2, l3};
    }
}

// ==================================================================
// Row softmax (causal), float4 loads, packed bf16 hi/lo stores
// ==================================================================
__global__ void __launch_bounds__(256) attn_softmax() {
    int q = blockIdx.x, bh = blockIdx.y;
    const float* row = g_scores + ((size_t)bh * Ss + q) * Ss;
    __nv_bfloat16* ph = g_ph + ((size_t)bh * Ss + q) * Ss;
    __nv_bfloat16* pl = g_pl + ((size_t)bh * Ss + q) * Ss;
    int klim = ((q >> 7) + 1) << 7;
    int t = threadIdx.x;
    int nc = (klim + 1023) >> 10;
    float4 v[2];
    float m = -1e30f;
    for (int c = 0; c < nc; c++) {
        int idx = t * 4 + c * 1024;
        if (idx < klim) {
            float4 x4 = *(const float4*)(row + idx);
            v[c].x = (idx + 0 <= q) ? x4.x : -1e30f;
            v[c].y = (idx + 1 <= q) ? x4.y : -1e30f;
            v[c].z = (idx + 2 <= q) ? x4.z : -1e30f;
            v[c].w = (idx + 3 <= q) ? x4.w : -1e30f;
            m = fmaxf(m, fmaxf(fmaxf(v[c].x, v[c].y), fmaxf(v[c].z, v[c].w)));
        } else {
            v[c] = float4{-1e30f, -1e30f, -1e30f, -1e30f};
        }
    }
    __shared__ float sh[32];
    int lane = t & 31, wp = t >> 5;
    #pragma unroll
    for (int o = 16; o; o >>= 1) m = fmaxf(m, __shfl_xor_sync(FULLMASK, m, o));
    if (lane == 0) sh[wp] = m;
    __syncthreads();
    if (wp == 0) {
        float x = (lane < 8) ? sh[lane] : -1e30f;
        #pragma unroll
        for (int o = 16; o; o >>= 1) x = fmaxf(x, __shfl_xor_sync(FULLMASK, x, o));
        if (lane == 0) sh[0] = x;
    }
    __syncthreads();
    m = sh[0];
    __syncthreads();
    float sum = 0.f;
    for (int c = 0; c < nc; c++) {
        v[c].x = __expf(v[c].x - m);
        v[c].y = __expf(v[c].y - m);
        v[c].z = __expf(v[c].z - m);
        v[c].w = __expf(v[c].w - m);
        sum += v[c].x + v[c].y + v[c].z + v[c].w;
    }
    #pragma unroll
    for (int o = 16; o; o >>= 1) sum += __shfl_xor_sync(FULLMASK, sum, o);
    if (lane == 0) sh[wp] = sum;
    __syncthreads();
    if (wp == 0) {
        float x = (lane < 8) ? sh[lane] : 0.f;
        #pragma unroll
        for (int o = 16; o; o >>= 1) x += __shfl_xor_sync(FULLMASK, x, o);
        if (lane == 0) sh[0] = x;
    }
    __syncthreads();
    float inv = 1.f / sh[0];
    for (int c = 0; c < nc; c++) {
        int idx = t * 4 + c * 1024;
        if (idx < klim) {
            float p0 = v[c].x * inv, p1 = v[c].y * inv;
            float p2 = v[c].z * inv, p3 = v[c].w * inv;
            __nv_bfloat16 h0, l0, h1, l1, h2, l2, h3, l3;
            bsplit(p0, h0, l0); bsplit(p1, h1, l1);
            bsplit(p2, h2, l2); bsplit(p3, h3, l3);
            __nv_bfloat162 hh[2] = {{h0, h1}, {h2, h3}};
            __nv_bfloat162 ll[2] = {{l0, l1}, {l2, l3}};
            *(uint2*)(ph + idx) = *(uint2*)hh;
            *(uint2*)(pl + idx) = *(uint2*)ll;
        }
    }
}

// ==================================================================
// launch
// ==================================================================
extern "C" void kernel_launch(void* const* d_in, const int* in_sizes, int n_in,
                              void* d_out, int out_size) {
    const float *x, *freqs, *tn_w, *tn_b, *alpha, *delta, *theta, *gamma, *omega, *rms_w;
    const float *wz_w, *wz_b, *wv_w, *wv_b, *wr_w, *wr_b, *wh1_w, *wh1_b, *wh2_w, *agam, *abeta;

    if (in_sizes[1] == Ss * 32 * 2) {
        x = (const float*)d_in[0];  freqs = (const float*)d_in[1];
        tn_w = (const float*)d_in[2]; tn_b = (const float*)d_in[3];
        alpha = (const float*)d_in[4]; delta = (const float*)d_in[5];
        theta = (const float*)d_in[6]; gamma = (const float*)d_in[7];
        omega = (const float*)d_in[8]; rms_w = (const float*)d_in[9];
        wz_w = (const float*)d_in[10]; wz_b = (const float*)d_in[11];
        wv_w = (const float*)d_in[12]; wv_b = (const float*)d_in[13];
        wr_w = (const float*)d_in[14]; wr_b = (const float*)d_in[15];
        wh1_w = (const float*)d_in[16]; wh1_b = (const float*)d_in[17];
        wh2_w = (const float*)d_in[18];
        agam = (const float*)d_in[19]; abeta = (const float*)d_in[20];
    } else {
        x = (const float*)d_in[0];
        tn_w = (const float*)d_in[1]; tn_b = (const float*)d_in[2];
        alpha = (const float*)d_in[3]; delta = (const float*)d_in[4];
        theta = (const float*)d_in[5]; gamma = (const float*)d_in[6];
        omega = (const float*)d_in[7]; rms_w = (const float*)d_in[8];
        wz_w = (const float*)d_in[9]; wz_b = (const float*)d_in[10];
        wv_w = (const float*)d_in[11]; wv_b = (const float*)d_in[12];
        wr_w = (const float*)d_in[13]; wr_b = (const float*)d_in[14];
        wh1_w = (const float*)d_in[15]; wh1_b = (const float*)d_in[16];
        wh2_w = (const float*)d_in[17];
        agam = (const float*)d_in[18]; abeta = (const float*)d_in[19];
        freqs = (const float*)d_in[20];
    }

    float* out = (float*)d_out;
    const int M = Bb * Ss;

    float *p_r;
    cudaGetSymbolAddress((void**)&p_r, g_r);
    __nv_bfloat16 *p_tsnh, *p_tsnl, *p_mxh, *p_mxl, *p_vh, *p_vl, *p_ath, *p_atl;
    __nv_bfloat16 *p_wzrh, *p_wzrl, *p_wvh, *p_wvl, *p_wh1h, *p_wh1l, *p_wh2h, *p_wh2l;
    cudaGetSymbolAddress((void**)&p_tsnh, g_tsnh); cudaGetSymbolAddress((void**)&p_tsnl, g_tsnl);
    cudaGetSymbolAddress((void**)&p_mxh, g_mxh);   cudaGetSymbolAddress((void**)&p_mxl, g_mxl);
    cudaGetSymbolAddress((void**)&p_vh, g_vh);     cudaGetSymbolAddress((void**)&p_vl, g_vl);
    cudaGetSymbolAddress((void**)&p_ath, g_ath);   cudaGetSymbolAddress((void**)&p_atl, g_atl);
    cudaGetSymbolAddress((void**)&p_wzrh, g_wzrh); cudaGetSymbolAddress((void**)&p_wzrl, g_wzrl);
    cudaGetSymbolAddress((void**)&p_wvh, g_wvh);   cudaGetSymbolAddress((void**)&p_wvl, g_wvl);
    cudaGetSymbolAddress((void**)&p_wh1h, g_wh1h); cudaGetSymbolAddress((void**)&p_wh1l, g_wh1l);
    cudaGetSymbolAddress((void**)&p_wh2h, g_wh2h); cudaGetSymbolAddress((void**)&p_wh2l, g_wh2l);

    cudaFuncSetAttribute(hgemm<false, false, true, false, false, true>,
                         cudaFuncAttributeMaxDynamicSharedMemorySize, HG_SMEM);
    cudaFuncSetAttribute(hgemm<true, false, true, true, false, false>,
                         cudaFuncAttributeMaxDynamicSharedMemorySize, HG_SMEM);
    cudaFuncSetAttribute(hgemm<false, true, true, false, true, false>,
                         cudaFuncAttributeMaxDynamicSharedMemorySize, HG_SMEM);
    cudaFuncSetAttribute(pv_hgemm, cudaFuncAttributeMaxDynamicSharedMemorySize, HG_SMEM);
    cudaFuncSetAttribute(attn_scores_mma, cudaFuncAttributeMaxDynamicSharedMemorySize, SC_SMEM);

    // batched weight splits (wz + wr fused into wzr[K, 4608])
    {
        SplitArgs sa;
        sa.src[0] = wz_w;  sa.h[0] = p_wzrh; sa.l[0] = p_wzrl;
        sa.srcW4[0] = Zz / 4;   sa.dstStride4[0] = NZR / 4; sa.dstOff4[0] = 0;
        sa.src[1] = wr_w;  sa.h[1] = p_wzrh; sa.l[1] = p_wzrl;
        sa.srcW4[1] = HDim / 4; sa.dstStride4[1] = NZR / 4; sa.dstOff4[1] = Zz / 4;
        sa.src[2] = wv_w;  sa.h[2] = p_wvh;  sa.l[2] = p_wvl;
        sa.srcW4[2] = HDim / 4; sa.dstStride4[2] = HDim / 4; sa.dstOff4[2] = 0;
        sa.src[3] = wh1_w; sa.h[3] = p_wh1h; sa.l[3] = p_wh1l;
        sa.srcW4[3] = Dd / 4;   sa.dstStride4[3] = Dd / 4;   sa.dstOff4[3] = 0;
        sa.src[4] = wh2_w; sa.h[4] = p_wh2h; sa.l[4] = p_wh2l;
        sa.srcW4[4] = Dd / 4;   sa.dstStride4[4] = Dd / 4;   sa.dstOff4[4] = 0;
        int n4s[5] = {Dd * Zz / 4, Dd * HDim / 4, Dd * HDim / 4, Dd * Dd / 4, HDim * Dd / 4};
        sa.cum[0] = 0;
        for (int i = 0; i < 5; i++) sa.cum[i + 1] = sa.cum[i] + n4s[i];
        splitk_all<<<(sa.cum[5] + 255) / 256, 256>>>(sa);
    }

    // timestep norm (writes bf16 hi/lo only)
    tsn_partial<<<(Bb * Ss * Gg) / 8, 256>>>(x);
    tsn_scan<<<Bb * Gg, 256>>>();
    tsn_norm<<<(Bb * Ss * Dd / 4) / 256, 256>>>(x, tn_w, tn_b);

    // cema (chunked, reads tsn hi/lo)
    cema_coef<<<(Dd * EN) / 256, 256>>>(alpha, delta, theta, gamma);
    cema_local<<<(Bb * NC * Dd) / 256, 256>>>();
    cema_prop<<<(Bb * Dd + 255) / 256, 256>>>();
    cema_final<<<(Bb * NC * Dd) / 256, 256>>>(omega);

    // mx = rmsnorm(cema)*w -> hi/lo
    rms_mx<<<M, 256>>>(rms_w);

    // fused: [z | r] = mx @ wzr ; z-half -> head-RMS + rotary -> q/k in epilogue
    {
        HgArgs a = {};
        a.Ah = p_mxh; a.Al = p_mxl; a.Bh = p_wzrh; a.Bl = p_wzrl;
        a.bias = wz_b; a.bias2 = wr_b; a.C2 = p_r;
        a.freqs = freqs; a.agam = agam; a.abeta = abeta;
        a.M = M; a.N = NZR; a.K = Dd; a.K1 = 1 << 30; a.lda1 = Dd; a.ldb = NZR;
        hgemm<false, false, true, false, false, true><<<dim3(NZR / 128, M / 128), 128, HG_SMEM>>>(a);
    }

    // v = silu(tsn @ wv + b) -> hi/lo
    {
        HgArgs a = {};
        a.Ah = p_tsnh; a.Al = p_tsnl; a.Bh = p_wvh; a.Bl = p_wvl;
        a.bias = wv_b; a.Ch = p_vh; a.Cl = p_vl;
        a.M = M; a.N = HDim; a.K = Dd; a.K1 = 1 << 30; a.lda1 = Dd; a.ldb = HDim;
        hgemm<true, false, true, true, false, false><<<dim3(HDim / 128, M / 128), 128, HG_SMEM>>>(a);
    }

    // attention
    attn_scores_mma<<<dim3(SC_TRI, 1, BHh), 128, SC_SMEM>>>();
    attn_softmax<<<dim3(Ss, BHh), 256>>>();
    pv_hgemm<<<dim3(VH / 128, Ss / 128, BHh), 128, HG_SMEM>>>(p_r);

    // out = [mx | attn] @ [wh1; wh2] + wh1_b + x   (fused K = 6144)
    {
        HgArgs a = {};
        a.Ah = p_mxh; a.Al = p_mxl; a.Bh = p_wh1h; a.Bl = p_wh1l;
        a.A2h = p_ath; a.A2l = p_atl; a.B2h = p_wh2h; a.B2l = p_wh2l;
        a.bias = wh1_b; a.resid = x; a.C = out;
        a.M = M; a.N = Dd; a.K = Dd + HDim; a.K1 = Dd;
        a.lda1 = Dd; a.lda2 = HDim; a.ldb = Dd;
        hgemm<false, true, true, false, true, false><<<dim3(Dd / 128, M / 128), 128, HG_SMEM>>>(a);
    }
}

// round 15
// speedup vs baseline: 1.0164x; 1.0164x over previous
#include <cuda_runtime.h>
#include <cuda_bf16.h>
#include <mma.h>
#include <math.h>
#include <stdint.h>

using namespace nvcuda;

#define FULLMASK 0xffffffffu

// ---------------- problem constants ----------------
constexpr int Bb = 2, Ss = 2048, Dd = 2048;
constexpr int Zz = 512, HDim = 4096, Hh = 8, EN = 8;
constexpr int ZH = 64, VH = 512;
constexpr int Gg = 32, DG = 64;
constexpr int BHh = Bb * Hh;
constexpr float EPSC = 1e-5f;
constexpr int NC = 16, CLk = Ss / NC;   // cema chunks
constexpr int NZR = Zz + HDim;          // fused z|r output width = 4608

// ---------------- scratch ----------------
__device__ float g_tsn [Bb * Ss * Dd];
__device__ float g_cema[Bb * Ss * Dd];
__device__ float g_z   [Bb * Ss * Zz];
__device__ float g_r   [Bb * Ss * HDim];
__device__ float g_scores[(size_t)BHh * Ss * Ss];
__device__ float g_p1[Bb * Gg * Ss];
__device__ float g_p2[Bb * Gg * Ss];
__device__ float g_c1[Bb * Gg * Ss];
__device__ float g_c2[Bb * Gg * Ss];
__device__ float g_coef[6][Dd * EN];
// cema chunk states
__device__ float g_sr[Bb][NC][EN][Dd], g_si[Bb][NC][EN][Dd];
__device__ float g_er[Bb][NC][EN][Dd], g_ei[Bb][NC][EN][Dd];

// bf16 hi/lo operands
__device__ __nv_bfloat16 g_tsnh[Bb * Ss * Dd],  g_tsnl[Bb * Ss * Dd];
__device__ __nv_bfloat16 g_mxh [Bb * Ss * Dd],  g_mxl [Bb * Ss * Dd];
__device__ __nv_bfloat16 g_vh  [Bb * Ss * HDim], g_vl [Bb * Ss * HDim];
__device__ __nv_bfloat16 g_ath [Bb * Ss * HDim], g_atl[Bb * Ss * HDim];
__device__ __nv_bfloat16 g_ph[(size_t)BHh * Ss * Ss], g_pl[(size_t)BHh * Ss * Ss];
__device__ __nv_bfloat16 g_qh [BHh * Ss * ZH],  g_ql [BHh * Ss * ZH];
__device__ __nv_bfloat16 g_kth[BHh * ZH * Ss],  g_ktl[BHh * ZH * Ss];
// weight splits (wz and wr fused column-wise into wzr[K, 4608])
__device__ __nv_bfloat16 g_wzrh[Dd * NZR],  g_wzrl[Dd * NZR];
__device__ __nv_bfloat16 g_wvh [Dd * HDim], g_wvl [Dd * HDim];
__device__ __nv_bfloat16 g_wh1h[Dd * Dd],   g_wh1l[Dd * Dd];
__device__ __nv_bfloat16 g_wh2h[HDim * Dd], g_wh2l[HDim * Dd];

// ---------------- helpers ----------------
__device__ __forceinline__ float sigmoidf_(float x) { return 1.f / (1.f + __expf(-x)); }

__device__ __forceinline__ void bsplit(float v, __nv_bfloat16& h, __nv_bfloat16& l) {
    h = __float2bfloat16(v);
    l = __float2bfloat16(v - __bfloat162float(h));
}

__device__ __forceinline__ uint32_t smem_u32(const void* p) {
    uint32_t a;
    asm("{ .reg .u64 t; cvta.to.shared.u64 t, %1; cvt.u32.u64 %0, t; }" : "=r"(a) : "l"(p));
    return a;
}

#define CP16(dst, src) \
    asm volatile("cp.async.cg.shared.global [%0], [%1], 16;" :: "r"(dst), "l"(src))
#define CP_COMMIT() asm volatile("cp.async.commit_group;" ::: "memory")
#define CP_WAIT0()  asm volatile("cp.async.wait_group 0;" ::: "memory")

// ---------------- batched split kernel w/ strided destinations ----------------
struct SplitArgs {
    const float* src[5];
    __nv_bfloat16 *h[5], *l[5];
    int cum[6];
    int srcW4[5];
    int dstStride4[5];
    int dstOff4[5];
};

__global__ void splitk_all(SplitArgs sa) {
    int i = blockIdx.x * blockDim.x + threadIdx.x;
    if (i >= sa.cum[5]) return;
    int s = 0;
    while (i >= sa.cum[s + 1]) s++;
    int j = i - sa.cum[s];
    int srow = j / sa.srcW4[s];
    int scol = j - srow * sa.srcW4[s];
    size_t dj = (size_t)srow * sa.dstStride4[s] + sa.dstOff4[s] + scol;
    float4 v = *(const float4*)(sa.src[s] + (size_t)j * 4);
    __nv_bfloat16 h0, l0, h1, l1, h2, l2, h3, l3;
    bsplit(v.x, h0, l0); bsplit(v.y, h1, l1);
    bsplit(v.z, h2, l2); bsplit(v.w, h3, l3);
    __nv_bfloat162* hp = (__nv_bfloat162*)(sa.h[s] + dj * 4);
    __nv_bfloat162* lp = (__nv_bfloat162*)(sa.l[s] + dj * 4);
    hp[0] = __nv_bfloat162{h0, h1}; hp[1] = __nv_bfloat162{h2, h3};
    lp[0] = __nv_bfloat162{l0, l1}; lp[1] = __nv_bfloat162{l2, l3};
}

// ==================================================================
// hgemm: bf16 hi/lo 3-product GEMM, 2-stage cp.async double buffer
// 128x128x32 CTA tile, 128 threads, 4 warps (2x2), warp tile 64x64
// ==================================================================
constexpr int ALD = 40;
constexpr int BLD = 136;
constexpr int CLD = 132;
constexpr int ST_AH = 0;
constexpr int ST_AL = ST_AH + 128 * ALD * 2;
constexpr int ST_BH = ST_AL + 128 * ALD * 2;
constexpr int ST_BL = ST_BH + 32 * BLD * 2;
constexpr int ST_SZ = ST_BL + 32 * BLD * 2;        // 37888
constexpr int HG_SMEM = (2 * ST_SZ > 128 * CLD * 4) ? 2 * ST_SZ : 128 * CLD * 4; // 75776

struct HgArgs {
    const __nv_bfloat16 *Ah, *Al, *Bh, *Bl;
    const __nv_bfloat16 *A2h, *A2l, *B2h, *B2l;
    const float *bias, *resid, *bias2;
    float *C, *C2;
    __nv_bfloat16 *Ch, *Cl;
    int M, N, K, K1, lda1, lda2, ldb;
};

template <bool FUSE>
__device__ __forceinline__ void hg_load_stage(uint32_t sb, const HgArgs& a,
                                              int m0, int n0, int k0, int tid) {
    const __nv_bfloat16 *Ah, *Al, *Bh, *Bl;
    int lda, kr;
    if (FUSE && k0 >= a.K1) {
        Ah = a.A2h; Al = a.A2l; Bh = a.B2h; Bl = a.B2l;
        lda = a.lda2; kr = k0 - a.K1;
    } else {
        Ah = a.Ah; Al = a.Al; Bh = a.Bh; Bl = a.Bl;
        lda = a.lda1; kr = k0;
    }
    #pragma unroll
    for (int i = 0; i < 4; i++) {
        int chunk = i * 128 + tid;
        int row = chunk >> 2, c = (chunk & 3) * 8;
        size_t go = (size_t)(m0 + row) * lda + kr + c;
        uint32_t so = sb + (uint32_t)((row * ALD + c) * 2);
        CP16(so + ST_AH, Ah + go);
        CP16(so + ST_AL, Al + go);
    }
    #pragma unroll
    for (int i = 0; i < 4; i++) {
        int chunk = i * 128 + tid;
        int row = chunk >> 4, c = (chunk & 15) * 8;
        size_t go = (size_t)(kr + row) * a.ldb + n0 + c;
        uint32_t so = sb + (uint32_t)((row * BLD + c) * 2);
        CP16(so + ST_BH, Bh + go);
        CP16(so + ST_BL, Bl + go);
    }
}

__device__ __forceinline__ void hg_mma64(char* st, int wm, int wn,
    wmma::fragment<wmma::accumulator, 16, 16, 16, float> (&acc)[4][4]) {
    __nv_bfloat16* Ah = (__nv_bfloat16*)(st + ST_AH);
    __nv_bfloat16* Al = (__nv_bfloat16*)(st + ST_AL);
    __nv_bfloat16* Bh = (__nv_bfloat16*)(st + ST_BH);
    __nv_bfloat16* Bl = (__nv_bfloat16*)(st + ST_BL);
    #pragma unroll
    for (int kk = 0; kk < 2; kk++) {
        wmma::fragment<wmma::matrix_a, 16, 16, 16, __nv_bfloat16, wmma::row_major> fah[4], fal[4];
        #pragma unroll
        for (int r = 0; r < 4; r++) {
            wmma::load_matrix_sync(fah[r], Ah + (wm + r * 16) * ALD + kk * 16, ALD);
            wmma::load_matrix_sync(fal[r], Al + (wm + r * 16) * ALD + kk * 16, ALD);
        }
        #pragma unroll
        for (int c = 0; c < 4; c++) {
            wmma::fragment<wmma::matrix_b, 16, 16, 16, __nv_bfloat16, wmma::row_major> fbh, fbl;
            wmma::load_matrix_sync(fbh, Bh + (kk * 16) * BLD + wn + c * 16, BLD);
            wmma::load_matrix_sync(fbl, Bl + (kk * 16) * BLD + wn + c * 16, BLD);
            #pragma unroll
            for (int r = 0; r < 4; r++) {
                wmma::mma_sync(acc[r][c], fah[r], fbh, acc[r][c]);
                wmma::mma_sync(acc[r][c], fah[r], fbl, acc[r][c]);
                wmma::mma_sync(acc[r][c], fal[r], fbh, acc[r][c]);
            }
        }
    }
}

template <bool SILU, bool RESID, bool BIAS, bool OUTHL, bool FUSE, bool ZR>
__global__ void __launch_bounds__(128) hgemm(HgArgs a) {
    extern __shared__ char sm[];
    const uint32_t sb0 = smem_u32(sm);
    float* Ct = (float*)sm;
    const int tid = threadIdx.x;
    const int wid = tid >> 5;
    const int m0 = blockIdx.y * 128;
    const int n0 = blockIdx.x * 128;
    const int wm = (wid & 1) * 64;
    const int wn = (wid >> 1) * 64;

    wmma::fragment<wmma::accumulator, 16, 16, 16, float> acc[4][4];
    #pragma unroll
    for (int r = 0; r < 4; r++)
        #pragma unroll
        for (int c = 0; c < 4; c++) wmma::fill_fragment(acc[r][c], 0.f);

    const int nk = a.K / 32;
    hg_load_stage<FUSE>(sb0, a, m0, n0, 0, tid);
    CP_COMMIT();

    for (int it = 0; it < nk; it++) {
        CP_WAIT0();
        __syncthreads();
        if (it + 1 < nk) {
            hg_load_stage<FUSE>(sb0 + ((it + 1) & 1) * ST_SZ, a, m0, n0, (it + 1) * 32, tid);
            CP_COMMIT();
        }
        hg_mma64(sm + (it & 1) * ST_SZ, wm, wn, acc);
    }
    __syncthreads();

    #pragma unroll
    for (int r = 0; r < 4; r++)
        #pragma unroll
        for (int c = 0; c < 4; c++)
            wmma::store_matrix_sync(Ct + (wm + r * 16) * CLD + wn + c * 16,
                                    acc[r][c], CLD, wmma::mem_row_major);
    __syncthreads();

    #pragma unroll
    for (int i = 0; i < 32; i++) {
        int flat = i * 128 + tid;
        int row = flat >> 5, col4 = (flat & 31) * 4;
        if (ZR) {
            int n = n0 + col4;
            if (n < Zz) {
                float v[4];
                #pragma unroll
                for (int e = 0; e < 4; e++)
                    v[e] = Ct[row * CLD + col4 + e] + a.bias[n + e];
                float4 o; o.x = v[0]; o.y = v[1]; o.z = v[2]; o.w = v[3];
                *(float4*)(a.C + (size_t)(m0 + row) * Zz + n) = o;
            } else {
                int nr = n - Zz;
                float v[4];
                #pragma unroll
                for (int e = 0; e < 4; e++) {
                    float cv = Ct[row * CLD + col4 + e] + a.bias2[nr + e];
                    v[e] = cv * sigmoidf_(cv);
                }
                float4 o; o.x = v[0]; o.y = v[1]; o.z = v[2]; o.w = v[3];
                *(float4*)(a.C2 + (size_t)(m0 + row) * HDim + nr) = o;
            }
        } else {
            size_t goff = (size_t)(m0 + row) * a.N + n0 + col4;
            float v[4];
            #pragma unroll
            for (int e = 0; e < 4; e++) {
                float cv = Ct[row * CLD + col4 + e];
                if (BIAS)  cv += a.bias[n0 + col4 + e];
                if (RESID) cv += a.resid[goff + e];
                if (SILU)  cv = cv * sigmoidf_(cv);
                v[e] = cv;
            }
            if (OUTHL) {
                __nv_bfloat16 h0, l0, h1, l1, h2, l2, h3, l3;
                bsplit(v[0], h0, l0); bsplit(v[1], h1, l1);
                bsplit(v[2], h2, l2); bsplit(v[3], h3, l3);
                __nv_bfloat162* hp = (__nv_bfloat162*)(a.Ch + goff);
                __nv_bfloat162* lp = (__nv_bfloat162*)(a.Cl + goff);
                hp[0] = __nv_bfloat162{h0, h1}; hp[1] = __nv_bfloat162{h2, h3};
                lp[0] = __nv_bfloat162{l0, l1}; lp[1] = __nv_bfloat162{l2, l3};
            } else {
                float4 o; o.x = v[0]; o.y = v[1]; o.z = v[2]; o.w = v[3];
                *(float4*)(a.C + goff) = o;
            }
        }
    }
}

// ==================================================================
// pv_hgemm: attn = (P @ V) * r -> bf16 hi/lo, 128 threads, 64x64 warp tile
// ==================================================================
__global__ void __launch_bounds__(128) pv_hgemm(const float* __restrict__ rgate) {
    extern __shared__ char sm[];
    const uint32_t sb0 = smem_u32(sm);
    float* Ct = (float*)sm;
    const int tid = threadIdx.x;
    const int wid = tid >> 5;
    const int nt = blockIdx.x;
    const int qt = (int)gridDim.y - 1 - (int)blockIdx.y;  // heavy tiles first
    const int bh = blockIdx.z;
    const int b = bh >> 3, h = bh & 7;
    const int wm = (wid & 1) * 64;
    const int wn = (wid >> 1) * 64;

    HgArgs a;
    a.Ah = g_ph + (size_t)bh * Ss * Ss + (size_t)(qt * 128) * Ss;
    a.Al = g_pl + (size_t)bh * Ss * Ss + (size_t)(qt * 128) * Ss;
    a.Bh = g_vh + (size_t)b * Ss * HDim + h * VH + nt * 128;
    a.Bl = g_vl + (size_t)b * Ss * HDim + h * VH + nt * 128;
    a.lda1 = Ss; a.ldb = HDim; a.K1 = 1 << 30;

    wmma::fragment<wmma::accumulator, 16, 16, 16, float> acc[4][4];
    #pragma unroll
    for (int r = 0; r < 4; r++)
        #pragma unroll
        for (int c = 0; c < 4; c++) wmma::fill_fragment(acc[r][c], 0.f);

    const int nk = (qt + 1) * 4;
    hg_load_stage<false>(sb0, a, 0, 0, 0, tid);
    CP_COMMIT();

    for (int it = 0; it < nk; it++) {
        CP_WAIT0();
        __syncthreads();
        if (it + 1 < nk) {
            hg_load_stage<false>(sb0 + ((it + 1) & 1) * ST_SZ, a, 0, 0, (it + 1) * 32, tid);
            CP_COMMIT();
        }
        hg_mma64(sm + (it & 1) * ST_SZ, wm, wn, acc);
    }
    __syncthreads();

    #pragma unroll
    for (int r = 0; r < 4; r++)
        #pragma unroll
        for (int c = 0; c < 4; c++)
            wmma::store_matrix_sync(Ct + (wm + r * 16) * CLD + wn + c * 16,
                                    acc[r][c], CLD, wmma::mem_row_major);
    __syncthreads();

    #pragma unroll
    for (int i = 0; i < 32; i++) {
        int flat = i * 128 + tid;
        int row = flat >> 5, col4 = (flat & 31) * 4;
        int q = qt * 128 + row;
        size_t goff = ((size_t)b * Ss + q) * HDim + h * VH + nt * 128 + col4;
        float4 rg = *(const float4*)(rgate + goff);
        float v0 = Ct[row * CLD + col4 + 0] * rg.x;
        float v1 = Ct[row * CLD + col4 + 1] * rg.y;
        float v2 = Ct[row * CLD + col4 + 2] * rg.z;
        float v3 = Ct[row * CLD + col4 + 3] * rg.w;
        __nv_bfloat16 h0, l0, h1, l1, h2, l2, h3, l3;
        bsplit(v0, h0, l0); bsplit(v1, h1, l1);
        bsplit(v2, h2, l2); bsplit(v3, h3, l3);
        __nv_bfloat162* hp = (__nv_bfloat162*)(g_ath + goff);
        __nv_bfloat162* lp = (__nv_bfloat162*)(g_atl + goff);
        hp[0] = __nv_bfloat162{h0, h1}; hp[1] = __nv_bfloat162{h2, h3};
        lp[0] = __nv_bfloat162{l0, l1}; lp[1] = __nv_bfloat162{l2, l3};
    }
}

// ==================================================================
// Attention scores via WMMA: triangular CTA grid (no empty CTAs),
// 128 threads, 4 warps (2x2), warp tile 64x64 (ratio 3)
// ==================================================================
constexpr int SC_QLD = 72;
constexpr int SC_KLD = 136;
constexpr int SC_QH = 0;
constexpr int SC_QL = SC_QH + 128 * SC_QLD * 2;
constexpr int SC_KH = SC_QL + 128 * SC_QLD * 2;
constexpr int SC_KL = SC_KH + 64 * SC_KLD * 2;
constexpr int SC_SMEM = SC_KL + 64 * SC_KLD * 2;
constexpr int SC_NT = Ss / 128;
constexpr int SC_TRI = SC_NT * (SC_NT + 1) / 2;

__global__ void __launch_bounds__(128) attn_scores_mma() {
    int t = blockIdx.x;
    int qt = (int)((sqrtf(8.f * (float)t + 1.f) - 1.f) * 0.5f);
    while ((qt + 1) * (qt + 2) / 2 <= t) qt++;
    while (qt * (qt + 1) / 2 > t) qt--;
    int kt = t - qt * (qt + 1) / 2;
    int bh = blockIdx.z;

    extern __shared__ char sm[];
    __nv_bfloat16* Qh = (__nv_bfloat16*)(sm + SC_QH);
    __nv_bfloat16* Ql = (__nv_bfloat16*)(sm + SC_QL);
    __nv_bfloat16* Kh = (__nv_bfloat16*)(sm + SC_KH);
    __nv_bfloat16* Kl = (__nv_bfloat16*)(sm + SC_KL);
    const int tid = threadIdx.x;
    const int wid = tid >> 5;
    const int wm = (wid & 1) * 64;
    const int wn = (wid >> 1) * 64;

    const __nv_bfloat16* qsrc_h = g_qh + ((size_t)bh * Ss + qt * 128) * ZH;
    const __nv_bfloat16* qsrc_l = g_ql + ((size_t)bh * Ss + qt * 128) * ZH;
    const __nv_bfloat16* ksrc_h = g_kth + (size_t)bh * ZH * Ss + kt * 128;
    const __nv_bfloat16* ksrc_l = g_ktl + (size_t)bh * ZH * Ss + kt * 128;

    #pragma unroll
    for (int i = 0; i < 8; i++) {
        int flat = i * 128 + tid;
        int row = flat >> 3, c8 = (flat & 7) * 8;
        *(uint4*)(Qh + row * SC_QLD + c8) = *(const uint4*)(qsrc_h + row * ZH + c8);
        *(uint4*)(Ql + row * SC_QLD + c8) = *(const uint4*)(qsrc_l + row * ZH + c8);
    }
    #pragma unroll
    for (int i = 0; i < 8; i++) {
        int flat = i * 128 + tid;
        int row = flat >> 4, c8 = (flat & 15) * 8;
        *(uint4*)(Kh + row * SC_KLD + c8) = *(const uint4*)(ksrc_h + (size_t)row * Ss + c8);
        *(uint4*)(Kl + row * SC_KLD + c8) = *(const uint4*)(ksrc_l + (size_t)row * Ss + c8);
    }
    __syncthreads();

    wmma::fragment<wmma::accumulator, 16, 16, 16, float> acc[4][4];
    #pragma unroll
    for (int r = 0; r < 4; r++)
        #pragma unroll
        for (int c = 0; c < 4; c++) wmma::fill_fragment(acc[r][c], 0.f);

    #pragma unroll
    for (int kk = 0; kk < 4; kk++) {
        wmma::fragment<wmma::matrix_a, 16, 16, 16, __nv_bfloat16, wmma::row_major> fah[4], fal[4];
        #pragma unroll
        for (int r = 0; r < 4; r++) {
            wmma::load_matrix_sync(fah[r], Qh + (wm + r * 16) * SC_QLD + kk * 16, SC_QLD);
            wmma::load_matrix_sync(fal[r], Ql + (wm + r * 16) * SC_QLD + kk * 16, SC_QLD);
        }
        #pragma unroll
        for (int c = 0; c < 4; c++) {
            wmma::fragment<wmma::matrix_b, 16, 16, 16, __nv_bfloat16, wmma::row_major> fbh, fbl;
            wmma::load_matrix_sync(fbh, Kh + (kk * 16) * SC_KLD + wn + c * 16, SC_KLD);
            wmma::load_matrix_sync(fbl, Kl + (kk * 16) * SC_KLD + wn + c * 16, SC_KLD);
            #pragma unroll
            for (int r = 0; r < 4; r++) {
                wmma::mma_sync(acc[r][c], fah[r], fbh, acc[r][c]);
                wmma::mma_sync(acc[r][c], fah[r], fbl, acc[r][c]);
                wmma::mma_sync(acc[r][c], fal[r], fbh, acc[r][c]);
            }
        }
    }

    #pragma unroll
    for (int r = 0; r < 4; r++)
        #pragma unroll
        for (int c = 0; c < 4; c++)
            wmma::store_matrix_sync(
                g_scores + ((size_t)bh * Ss + qt * 128 + wm + r * 16) * Ss + kt * 128 + wn + c * 16,
                acc[r][c], Ss, wmma::mem_row_major);
}

// ==================================================================
// Timestep norm
// ==================================================================
__global__ void tsn_partial(const float* __restrict__ x) {
    int warp = (blockIdx.x * blockDim.x + threadIdx.x) >> 5;
    int lane = threadIdx.x & 31;
    if (warp >= Bb * Ss * Gg) return;
    int g = warp % Gg;
    int s = (warp / Gg) % Ss;
    int b = warp / (Gg * Ss);
    const float* p = x + ((size_t)(b * Ss + s)) * Dd + g * DG;
    float v0 = p[lane], v1 = p[lane + 32];
    float s1 = v0 + v1;
    float s2 = v0 * v0 + v1 * v1;
    #pragma unroll
    for (int o = 16; o; o >>= 1) {
        s1 += __shfl_down_sync(FULLMASK, s1, o);
        s2 += __shfl_down_sync(FULLMASK, s2, o);
    }
    if (lane == 0) {
        int idx = (b * Gg + g) * Ss + s;
        g_p1[idx] = s1;
        g_p2[idx] = s2;
    }
}

__global__ void tsn_scan() {
    int bg = blockIdx.x;
    int t  = threadIdx.x;
    const float* r1 = g_p1 + bg * Ss;
    const float* r2 = g_p2 + bg * Ss;
    float v1[8], v2[8];
    float a1 = 0.f, a2 = 0.f;
    #pragma unroll
    for (int i = 0; i < 8; i++) {
        a1 += r1[t * 8 + i]; v1[i] = a1;
        a2 += r2[t * 8 + i]; v2[i] = a2;
    }
    __shared__ float sh1[256], sh2[256];
    sh1[t] = a1; sh2[t] = a2;
    __syncthreads();
    for (int off = 1; off < 256; off <<= 1) {
        float b1 = 0.f, b2 = 0.f;
        if (t >= off) { b1 = sh1[t - off]; b2 = sh2[t - off]; }
        __syncthreads();
        sh1[t] += b1; sh2[t] += b2;
        __syncthreads();
    }
    float o1 = t ? sh1[t - 1] : 0.f;
    float o2 = t ? sh2[t - 1] : 0.f;
    float* w1 = g_c1 + bg * Ss;
    float* w2 = g_c2 + bg * Ss;
    #pragma unroll
    for (int i = 0; i < 8; i++) {
        w1[t * 8 + i] = v1[i] + o1;
        w2[t * 8 + i] = v2[i] + o2;
    }
}

__global__ void tsn_norm(const float* __restrict__ x, const float* __restrict__ w,
                         const float* __restrict__ bias) {
    int i4 = blockIdx.x * blockDim.x + threadIdx.x;
    if (i4 >= Bb * Ss * Dd / 4) return;
    int d4 = i4 % (Dd / 4);
    int s  = (i4 / (Dd / 4)) % Ss;
    int b  = i4 / (Dd / 4 * Ss);
    int d  = d4 * 4;
    int g  = d / DG;
    int ci = (b * Gg + g) * Ss + s;
    float cnt  = (float)(s + 1) * (float)DG;
    float mean = g_c1[ci] / cnt;
    float var  = g_c2[ci] / cnt - mean * mean;
    float inv  = rsqrtf(var + EPSC);
    float4 xv = *(const float4*)(x + (size_t)i4 * 4);
    float4 wv = *(const float4*)(w + d);
    float4 bv = *(const float4*)(bias + d);
    float4 o;
    o.x = (xv.x - mean) * inv * wv.x + bv.x;
    o.y = (xv.y - mean) * inv * wv.y + bv.y;
    o.z = (xv.z - mean) * inv * wv.z + bv.z;
    o.w = (xv.w - mean) * inv * wv.w + bv.w;
    *(float4*)(g_tsn + (size_t)i4 * 4) = o;
    __nv_bfloat16 h0, l0, h1, l1, h2, l2, h3, l3;
    bsplit(o.x, h0, l0); bsplit(o.y, h1, l1);
    bsplit(o.z, h2, l2); bsplit(o.w, h3, l3);
    __nv_bfloat162* hp = (__nv_bfloat162*)(g_tsnh + (size_t)i4 * 4);
    __nv_bfloat162* lp = (__nv_bfloat162*)(g_tsnl + (size_t)i4 * 4);
    hp[0] = __nv_bfloat162{h0, h1}; hp[1] = __nv_bfloat162{h2, h3};
    lp[0] = __nv_bfloat162{l0, l1}; lp[1] = __nv_bfloat162{l2, l3};
}

// ==================================================================
// CEMA (chunked scan)
// ==================================================================
__global__ void cema_coef(const float* __restrict__ alpha, const float* __restrict__ delta,
                          const float* __restrict__ theta, const float* __restrict__ gamma) {
    int i = blockIdx.x * blockDim.x + threadIdx.x;
    if (i >= Dd * EN) return;
    int d = i / EN, n = i % EN;
    float p  = 1.f / (1.f + expf(-alpha[i]));
    float qm = 1.f - p * (1.f / (1.f + expf(-delta[i])));
    float th = 1.f / (1.f + expf(-theta[d]));
    float ph = th * (2.f * 3.14159265358979323846f * (float)(n + 1) / (float)EN);
    float c = cosf(ph), s = sinf(ph);
    g_coef[0][i] = qm * c;
    g_coef[1][i] = qm * s;
    g_coef[2][i] = p * c;
    g_coef[3][i] = p * s;
    g_coef[4][i] = gamma[i * 2 + 0];
    g_coef[5][i] = gamma[i * 2 + 1];
}

__global__ void cema_local() {
    int gt = blockIdx.x * blockDim.x + threadIdx.x;
    if (gt >= Bb * NC * Dd) return;
    int d = gt % Dd;
    int c = (gt / Dd) % NC;
    int b = gt / (Dd * NC);
    float qr[8], qi[8], ur[8], ui[8], hr[8], hi[8];
    #pragma unroll
    for (int n = 0; n < EN; n++) {
        int ci = d * EN + n;
        qr[n] = g_coef[0][ci]; qi[n] = g_coef[1][ci];
        ur[n] = g_coef[2][ci]; ui[n] = g_coef[3][ci];
        hr[n] = 0.f; hi[n] = 0.f;
    }
    const float* xp = g_tsn + ((size_t)b * Ss + c * CLk) * Dd + d;
    float xv = xp[0];
    for (int t = 0; t < CLk; t++) {
        float xnext = (t + 1 < CLk) ? xp[(size_t)(t + 1) * Dd] : 0.f;
        #pragma unroll
        for (int n = 0; n < EN; n++) {
            float nhr = fmaf(qr[n], hr[n], fmaf(-qi[n], hi[n], ur[n] * xv));
            float nhi = fmaf(qi[n], hr[n], fmaf(qr[n], hi[n], ui[n] * xv));
            hr[n] = nhr; hi[n] = nhi;
        }
        xv = xnext;
    }
    #pragma unroll
    for (int n = 0; n < EN; n++) {
        g_sr[b][c][n][d] = hr[n];
        g_si[b][c][n][d] = hi[n];
    }
}

__global__ void cema_prop() {
    int gt = blockIdx.x * blockDim.x + threadIdx.x;
    if (gt >= Bb * Dd) return;
    int d = gt % Dd, b = gt / Dd;
    #pragma unroll
    for (int n = 0; n < EN; n++) {
        int ci = d * EN + n;
        float pr = g_coef[0][ci], pi = g_coef[1][ci];
        #pragma unroll
        for (int s = 0; s < 7; s++) {
            float nr = pr * pr - pi * pi;
            float ni = 2.f * pr * pi;
            pr = nr; pi = ni;
        }
        float er = 0.f, ei = 0.f;
        for (int c = 0; c < NC; c++) {
            g_er[b][c][n][d] = er;
            g_ei[b][c][n][d] = ei;
            float sr = g_sr[b][c][n][d], si = g_si[b][c][n][d];
            float nr = fmaf(pr, er, fmaf(-pi, ei, sr));
            float ni = fmaf(pi, er, fmaf(pr, ei, si));
            er = nr; ei = ni;
        }
    }
}

__global__ void cema_final(const float* __restrict__ omega) {
    int gt = blockIdx.x * blockDim.x + threadIdx.x;
    if (gt >= Bb * NC * Dd) return;
    int d = gt % Dd;
    int c = (gt / Dd) % NC;
    int b = gt / (Dd * NC);
    float qr[8], qi[8], ur[8], ui[8], gr[8], gi[8], hr[8], hi[8];
    #pragma unroll
    for (int n = 0; n < EN; n++) {
        int ci = d * EN + n;
        qr[n] = g_coef[0][ci]; qi[n] = g_coef[1][ci];
        ur[n] = g_coef[2][ci]; ui[n] = g_coef[3][ci];
        gr[n] = g_coef[4][ci]; gi[n] = g_coef[5][ci];
        hr[n] = g_er[b][c][n][d];
        hi[n] = g_ei[b][c][n][d];
    }
    float om = omega[d];
    const float* xp = g_tsn + ((size_t)b * Ss + c * CLk) * Dd + d;
    float* op = g_cema + ((size_t)b * Ss + c * CLk) * Dd + d;
    float xv = xp[0];
    for (int t = 0; t < CLk; t++) {
        float xnext = (t + 1 < CLk) ? xp[(size_t)(t + 1) * Dd] : 0.f;
        float y = 0.f;
        #pragma unroll
        for (int n = 0; n < EN; n++) {
            float nhr = fmaf(qr[n], hr[n], fmaf(-qi[n], hi[n], ur[n] * xv));
            float nhi = fmaf(qi[n], hr[n], fmaf(qr[n], hi[n], ui[n] * xv));
            hr[n] = nhr; hi[n] = nhi;
            y = fmaf(nhr, gr[n], fmaf(nhi, gi[n], y));
        }
        op[(size_t)t * Dd] = fmaf(xv, om, y);
        xv = xnext;
    }
}

// ==================================================================
// RMSNorm over D -> mx hi/lo
// ==================================================================
__global__ void rms_mx(const float* __restrict__ w) {
    int row = blockIdx.x;
    int t = threadIdx.x;
    const float* xr = g_cema + (size_t)row * Dd;
    float4 xv[2];
    float ss = 0.f;
    #pragma unroll
    for (int i = 0; i < 2; i++) {
        xv[i] = *(const float4*)(xr + (t + i * 256) * 4);
        ss += xv[i].x * xv[i].x + xv[i].y * xv[i].y + xv[i].z * xv[i].z + xv[i].w * xv[i].w;
    }
    __shared__ float sh[32];
    int lane = t & 31, wp = t >> 5;
    #pragma unroll
    for (int o = 16; o; o >>= 1) ss += __shfl_xor_sync(FULLMASK, ss, o);
    if (lane == 0) sh[wp] = ss;
    __syncthreads();
    if (wp == 0) {
        float v = (lane < 8) ? sh[lane] : 0.f;
        #pragma unroll
        for (int o = 16; o; o >>= 1) v += __shfl_xor_sync(FULLMASK, v, o);
        if (lane == 0) sh[0] = v;
    }
    __syncthreads();
    float inv = rsqrtf(sh[0] / (float)Dd + EPSC);
    #pragma unroll
    for (int i = 0; i < 2; i++) {
        int c = (t + i * 256) * 4;
        float4 wv = *(const float4*)(w + c);
        float o0 = xv[i].x * inv * wv.x;
        float o1 = xv[i].y * inv * wv.y;
        float o2 = xv[i].z * inv * wv.z;
        float o3 = xv[i].w * inv * wv.w;
        __nv_bfloat16 h0, l0, h1, l1, h2, l2, h3, l3;
        bsplit(o0, h0, l0); bsplit(o1, h1, l1);
        bsplit(o2, h2, l2); bsplit(o3, h3, l3);
        size_t off = (size_t)row * Dd + c;
        __nv_bfloat162* hp = (__nv_bfloat162*)(g_mxh + off);
        __nv_bfloat162* lp = (__nv_bfloat162*)(g_mxl + off);
        hp[0] = __nv_bfloat162{h0, h1}; hp[1] = __nv_bfloat162{h2, h3};
        lp[0] = __nv_bfloat162{l0, l1}; lp[1] = __nv_bfloat162{l2, l3};
    }
}

// ==================================================================
// z head-RMS + gamma/beta + rotary -> bf16 hi/lo Q and K-transposed
// ==================================================================
__global__ void qk_prep(const float* __restrict__ freqs, const float* __restrict__ agam,
                        const float* __restrict__ abeta) {
    int bs = blockIdx.x;
    int h = threadIdx.x >> 5, lane = threadIdx.x & 31;
    int b = bs / Ss, s = bs % Ss;
    const float* zr = g_z + (size_t)bs * Zz + h * ZH;
    float z0 = zr[2 * lane], z1 = zr[2 * lane + 1];
    float ss = z0 * z0 + z1 * z1;
    #pragma unroll
    for (int o = 16; o; o >>= 1) ss += __shfl_xor_sync(FULLMASK, ss, o);
    float inv = rsqrtf(ss / (float)ZH + EPSC);
    z0 *= inv; z1 *= inv;
    int j = h * ZH + 2 * lane;
    const float c0 = 0.125f;
    float gq0 = (agam[j] + 1.f) * c0,      gq1 = (agam[j + 1] + 1.f) * c0;
    float gk0 = (agam[Zz + j] + 1.f) * c0, gk1 = (agam[Zz + j + 1] + 1.f) * c0;
    float q0 = z0 * gq0 + abeta[j],        q1 = z1 * gq1 + abeta[j + 1];
    float k0 = z0 * gk0 + abeta[Zz + j],   k1 = z1 * gk1 + abeta[Zz + j + 1];
    float cv = freqs[(s * 32 + lane) * 2 + 0];
    float sv = freqs[(s * 32 + lane) * 2 + 1];
    float qa = q0 * cv - q1 * sv, qb = q0 * sv + q1 * cv;
    float ka = k0 * cv - k1 * sv, kb = k0 * sv + k1 * cv;

    size_t qbase = ((size_t)(b * Hh + h) * Ss + s) * ZH + 2 * lane;
    __nv_bfloat16 ha, la, hb, lb;
    bsplit(qa, ha, la); bsplit(qb, hb, lb);
    g_qh[qbase] = ha; g_qh[qbase + 1] = hb;
    g_ql[qbase] = la; g_ql[qbase + 1] = lb;

    size_t kbase = ((size_t)(b * Hh + h) * ZH + 2 * lane) * Ss + s;
    bsplit(ka, ha, la); bsplit(kb, hb, lb);
    g_kth[kbase] = ha; g_kth[kbase + Ss] = hb;
    g_ktl[kbase] = la; g_ktl[kbase + Ss] = lb;
}

// ==================================================================
// Row softmax (causal): paired rows (q, Ss-1-q) per block for balance
// ==================================================================
__device__ __forceinline__ void softmax_row(int q, int bh) {
    const float* row = g_scores + ((size_t)bh * Ss + q) * Ss;
    __nv_bfloat16* ph = g_ph + ((size_t)bh * Ss + q) * Ss;
    __nv_bfloat16* pl = g_pl + ((size_t)bh * Ss + q) * Ss;
    int klim = ((q >> 7) + 1) << 7;
    int t = threadIdx.x;
    int nc = (klim + 1023) >> 10;
    float4 v[2];
    float m = -1e30f;
    for (int c = 0; c < nc; c++) {
        int idx = t * 4 + c * 1024;
        if (idx < klim) {
            float4 x4 = *(const float4*)(row + idx);
            v[c].x = (idx + 0 <= q) ? x4.x : -1e30f;
            v[c].y = (idx + 1 <= q) ? x4.y : -1e30f;
            v[c].z = (idx + 2 <= q) ? x4.z : -1e30f;
            v[c].w = (idx + 3 <= q) ? x4.w : -1e30f;
            m = fmaxf(m, fmaxf(fmaxf(v[c].x, v[c].y), fmaxf(v[c].z, v[c].w)));
        } else {
            v[c] = float4{-1e30f, -1e30f, -1e30f, -1e30f};
        }
    }
    __shared__ float sh[32];
    int lane = t & 31, wp = t >> 5;
    #pragma unroll
    for (int o = 16; o; o >>= 1) m = fmaxf(m, __shfl_xor_sync(FULLMASK, m, o));
    if (lane == 0) sh[wp] = m;
    __syncthreads();
    if (wp == 0) {
        float x = (lane < 8) ? sh[lane] : -1e30f;
        #pragma unroll
        for (int o = 16; o; o >>= 1) x = fmaxf(x, __shfl_xor_sync(FULLMASK, x, o));
        if (lane == 0) sh[0] = x;
    }
    __syncthreads();
    m = sh[0];
    __syncthreads();
    float sum = 0.f;
    for (int c = 0; c < nc; c++) {
        v[c].x = __expf(v[c].x - m);
        v[c].y = __expf(v[c].y - m);
        v[c].z = __expf(v[c].z - m);
        v[c].w = __expf(v[c].w - m);
        sum += v[c].x + v[c].y + v[c].z + v[c].w;
    }
    #pragma unroll
    for (int o = 16; o; o >>= 1) sum += __shfl_xor_sync(FULLMASK, sum, o);
    if (lane == 0) sh[wp] = sum;
    __syncthreads();
    if (wp == 0) {
        float x = (lane < 8) ? sh[lane] : 0.f;
        #pragma unroll
        for (int o = 16; o; o >>= 1) x += __shfl_xor_sync(FULLMASK, x, o);
        if (lane == 0) sh[0] = x;
    }
    __syncthreads();
    float inv = 1.f / sh[0];
    for (int c = 0; c < nc; c++) {
        int idx = t * 4 + c * 1024;
        if (idx < klim) {
            float p0 = v[c].x * inv, p1 = v[c].y * inv;
            float p2 = v[c].z * inv, p3 = v[c].w * inv;
            __nv_bfloat16 h0, l0, h1, l1, h2, l2, h3, l3;
            bsplit(p0, h0, l0); bsplit(p1, h1, l1);
            bsplit(p2, h2, l2); bsplit(p3, h3, l3);
            __nv_bfloat162 hh[2] = {{h0, h1}, {h2, h3}};
            __nv_bfloat162 ll[2] = {{l0, l1}, {l2, l3}};
            *(uint2*)(ph + idx) = *(uint2*)hh;
            *(uint2*)(pl + idx) = *(uint2*)ll;
        }
    }
    __syncthreads();
}

__global__ void __launch_bounds__(256) attn_softmax() {
    int bh = blockIdx.y;
    softmax_row(blockIdx.x, bh);               // short row
    softmax_row(Ss - 1 - (int)blockIdx.x, bh); // long row
}

// ==================================================================
// launch
// ==================================================================
extern "C" void kernel_launch(void* const* d_in, const int* in_sizes, int n_in,
                              void* d_out, int out_size) {
    const float *x, *freqs, *tn_w, *tn_b, *alpha, *delta, *theta, *gamma, *omega, *rms_w;
    const float *wz_w, *wz_b, *wv_w, *wv_b, *wr_w, *wr_b, *wh1_w, *wh1_b, *wh2_w, *agam, *abeta;

    if (in_sizes[1] == Ss * 32 * 2) {
        x = (const float*)d_in[0];  freqs = (const float*)d_in[1];
        tn_w = (const float*)d_in[2]; tn_b = (const float*)d_in[3];
        alpha = (const float*)d_in[4]; delta = (const float*)d_in[5];
        theta = (const float*)d_in[6]; gamma = (const float*)d_in[7];
        omega = (const float*)d_in[8]; rms_w = (const float*)d_in[9];
        wz_w = (const float*)d_in[10]; wz_b = (const float*)d_in[11];
        wv_w = (const float*)d_in[12]; wv_b = (const float*)d_in[13];
        wr_w = (const float*)d_in[14]; wr_b = (const float*)d_in[15];
        wh1_w = (const float*)d_in[16]; wh1_b = (const float*)d_in[17];
        wh2_w = (const float*)d_in[18];
        agam = (const float*)d_in[19]; abeta = (const float*)d_in[20];
    } else {
        x = (const float*)d_in[0];
        tn_w = (const float*)d_in[1]; tn_b = (const float*)d_in[2];
        alpha = (const float*)d_in[3]; delta = (const float*)d_in[4];
        theta = (const float*)d_in[5]; gamma = (const float*)d_in[6];
        omega = (const float*)d_in[7]; rms_w = (const float*)d_in[8];
        wz_w = (const float*)d_in[9]; wz_b = (const float*)d_in[10];
        wv_w = (const float*)d_in[11]; wv_b = (const float*)d_in[12];
        wr_w = (const float*)d_in[13]; wr_b = (const float*)d_in[14];
        wh1_w = (const float*)d_in[15]; wh1_b = (const float*)d_in[16];
        wh2_w = (const float*)d_in[17];
        agam = (const float*)d_in[18]; abeta = (const float*)d_in[19];
        freqs = (const float*)d_in[20];
    }

    float* out = (float*)d_out;
    const int M = Bb * Ss;

    float *p_z, *p_r;
    cudaGetSymbolAddress((void**)&p_z, g_z);
    cudaGetSymbolAddress((void**)&p_r, g_r);
    __nv_bfloat16 *p_tsnh, *p_tsnl, *p_mxh, *p_mxl, *p_vh, *p_vl, *p_ath, *p_atl;
    __nv_bfloat16 *p_wzrh, *p_wzrl, *p_wvh, *p_wvl, *p_wh1h, *p_wh1l, *p_wh2h, *p_wh2l;
    cudaGetSymbolAddress((void**)&p_tsnh, g_tsnh); cudaGetSymbolAddress((void**)&p_tsnl, g_tsnl);
    cudaGetSymbolAddress((void**)&p_mxh, g_mxh);   cudaGetSymbolAddress((void**)&p_mxl, g_mxl);
    cudaGetSymbolAddress((void**)&p_vh, g_vh);     cudaGetSymbolAddress((void**)&p_vl, g_vl);
    cudaGetSymbolAddress((void**)&p_ath, g_ath);   cudaGetSymbolAddress((void**)&p_atl, g_atl);
    cudaGetSymbolAddress((void**)&p_wzrh, g_wzrh); cudaGetSymbolAddress((void**)&p_wzrl, g_wzrl);
    cudaGetSymbolAddress((void**)&p_wvh, g_wvh);   cudaGetSymbolAddress((void**)&p_wvl, g_wvl);
    cudaGetSymbolAddress((void**)&p_wh1h, g_wh1h); cudaGetSymbolAddress((void**)&p_wh1l, g_wh1l);
    cudaGetSymbolAddress((void**)&p_wh2h, g_wh2h); cudaGetSymbolAddress((void**)&p_wh2l, g_wh2l);

    cudaFuncSetAttribute(hgemm<false, false, true, false, false, true>,
                         cudaFuncAttributeMaxDynamicSharedMemorySize, HG_SMEM);
    cudaFuncSetAttribute(hgemm<true, false, true, true, false, false>,
                         cudaFuncAttributeMaxDynamicSharedMemorySize, HG_SMEM);
    cudaFuncSetAttribute(hgemm<false, true, true, false, true, false>,
                         cudaFuncAttributeMaxDynamicSharedMemorySize, HG_SMEM);
    cudaFuncSetAttribute(pv_hgemm, cudaFuncAttributeMaxDynamicSharedMemorySize, HG_SMEM);
    cudaFuncSetAttribute(attn_scores_mma, cudaFuncAttributeMaxDynamicSharedMemorySize, SC_SMEM);

    // batched weight splits (wz + wr fused into wzr[K, 4608])
    {
        SplitArgs sa;
        sa.src[0] = wz_w;  sa.h[0] = p_wzrh; sa.l[0] = p_wzrl;
        sa.srcW4[0] = Zz / 4;   sa.dstStride4[0] = NZR / 4; sa.dstOff4[0] = 0;
        sa.src[1] = wr_w;  sa.h[1] = p_wzrh; sa.l[1] = p_wzrl;
        sa.srcW4[1] = HDim / 4; sa.dstStride4[1] = NZR / 4; sa.dstOff4[1] = Zz / 4;
        sa.src[2] = wv_w;  sa.h[2] = p_wvh;  sa.l[2] = p_wvl;
        sa.srcW4[2] = HDim / 4; sa.dstStride4[2] = HDim / 4; sa.dstOff4[2] = 0;
        sa.src[3] = wh1_w; sa.h[3] = p_wh1h; sa.l[3] = p_wh1l;
        sa.srcW4[3] = Dd / 4;   sa.dstStride4[3] = Dd / 4;   sa.dstOff4[3] = 0;
        sa.src[4] = wh2_w; sa.h[4] = p_wh2h; sa.l[4] = p_wh2l;
        sa.srcW4[4] = Dd / 4;   sa.dstStride4[4] = Dd / 4;   sa.dstOff4[4] = 0;
        int n4s[5] = {Dd * Zz / 4, Dd * HDim / 4, Dd * HDim / 4, Dd * Dd / 4, HDim * Dd / 4};
        sa.cum[0] = 0;
        for (int i = 0; i < 5; i++) sa.cum[i + 1] = sa.cum[i] + n4s[i];
        splitk_all<<<(sa.cum[5] + 255) / 256, 256>>>(sa);
    }

    // timestep norm
    tsn_partial<<<(Bb * Ss * Gg) / 8, 256>>>(x);
    tsn_scan<<<Bb * Gg, 256>>>();
    tsn_norm<<<(Bb * Ss * Dd / 4) / 256, 256>>>(x, tn_w, tn_b);

    // cema (chunked)
    cema_coef<<<(Dd * EN) / 256, 256>>>(alpha, delta, theta, gamma);
    cema_local<<<(Bb * NC * Dd) / 256, 256>>>();
    cema_prop<<<(Bb * Dd + 255) / 256, 256>>>();
    cema_final<<<(Bb * NC * Dd) / 256, 256>>>(omega);

    // mx = rmsnorm(cema)*w -> hi/lo
    rms_mx<<<M, 256>>>(rms_w);

    // fused: [z | r] = mx @ wzr  (z += wz_b; r = silu(. + wr_b))
    {
        HgArgs a = {};
        a.Ah = p_mxh; a.Al = p_mxl; a.Bh = p_wzrh; a.Bl = p_wzrl;
        a.bias = wz_b; a.bias2 = wr_b; a.C = p_z; a.C2 = p_r;
        a.M = M; a.N = NZR; a.K = Dd; a.K1 = 1 << 30; a.lda1 = Dd; a.ldb = NZR;
        hgemm<false, false, true, false, false, true><<<dim3(NZR / 128, M / 128), 128, HG_SMEM>>>(a);
    }
    qk_prep<<<M, 256>>>(freqs, agam, abeta);

    // v = silu(tsn @ wv + b) -> hi/lo
    {
        HgArgs a = {};
        a.Ah = p_tsnh; a.Al = p_tsnl; a.Bh = p_wvh; a.Bl = p_wvl;
        a.bias = wv_b; a.Ch = p_vh; a.Cl = p_vl;
        a.M = M; a.N = HDim; a.K = Dd; a.K1 = 1 << 30; a.lda1 = Dd; a.ldb = HDim;
        hgemm<true, false, true, true, false, false><<<dim3(HDim / 128, M / 128), 128, HG_SMEM>>>(a);
    }

    // attention
    attn_scores_mma<<<dim3(SC_TRI, 1, BHh), 128, SC_SMEM>>>();
    attn_softmax<<<dim3(Ss / 2, BHh), 256>>>();
    pv_hgemm<<<dim3(VH / 128, Ss / 128, BHh), 128, HG_SMEM>>>(p_r);

    // out = [mx | attn] @ [wh1; wh2] + wh1_b + x   (fused K = 6144)
    {
        HgArgs a = {};
        a.Ah = p_mxh; a.Al = p_mxl; a.Bh = p_wh1h; a.Bl = p_wh1l;
        a.A2h = p_ath; a.A2l = p_atl; a.B2h = p_wh2h; a.B2l = p_wh2l;
        a.bias = wh1_b; a.resid = x; a.C = out;
        a.M = M; a.N = Dd; a.K = Dd + HDim; a.K1 = Dd;
        a.lda1 = Dd; a.lda2 = HDim; a.ldb = Dd;
        hgemm<false, true, true, false, true, false><<<dim3(Dd / 128, M / 128), 128, HG_SMEM>>>(a);
    }
}